// round 13
// baseline (speedup 1.0000x reference)
#include <cuda_runtime.h>
#include <cuda_bf16.h>
#include <math.h>
#include <stdint.h>

#define NSENT 64
#define S_LEN 512
#define D_DIM 768
#define NL    128
#define HID   512
#define CLS   3
#define E_MAX 2000
#define P_MAX 20000
#define NBIG  1152            // 512(A0) + 512(B0) + 128(x0)
#define KS    1536            // 2*768: [hi | lo]
#define KSC   256             // 2*128: [hi | lo]
#define BKH   32              // K-halves per chunk
#define NCH2  (D_DIM / BKH)   // 24
#define NCHC2 (NL / BKH)      // 4

// ---------------- static device scratch ----------------
__device__ __nv_bfloat16 g_Acat[E_MAX * KS];     // [hi | lo]
__device__ __nv_bfloat16 g_Bcat[NBIG * KS];      // W^T, [hi | lo]
__device__ __nv_bfloat16 g_W1cT[HID * KSC];      // W1c^T, [hi | lo]
__device__ __nv_bfloat16 g_xcat[E_MAX * KSC];    // x split [hi | lo]
__device__ float g_ABX  [E_MAX * NBIG];          // [A0 | B0 | x0]
__device__ float g_Ap   [E_MAX * HID];           // A0 + C + b1
__device__ float g_Bp   [E_MAX * HID];           // B0 - C
__device__ float g_xbuf [2][E_MAX * NL];
__device__ float g_sintra[2][E_MAX * NL];
__device__ float g_sinter[2][E_MAX * NL];
__device__ float g_cintra[2][E_MAX];
__device__ float g_cinter[2][E_MAX];
__device__ float g_Wcat [3 * NL * NL];
__device__ float g_losspart[4];

// ---------------- warp-mma / cp.async helpers ----------------
__device__ __forceinline__ uint32_t smem_u32(const void* p) {
    uint32_t a;
    asm("{ .reg .u64 t; cvta.to.shared.u64 t, %1; cvt.u32.u64 %0, t; }"
        : "=r"(a) : "l"(p));
    return a;
}
__device__ __forceinline__ void ldmatrix_x4(uint32_t* r, uint32_t addr) {
    asm volatile("ldmatrix.sync.aligned.m8n8.x4.shared.b16 {%0,%1,%2,%3}, [%4];"
                 : "=r"(r[0]), "=r"(r[1]), "=r"(r[2]), "=r"(r[3]) : "r"(addr));
}
__device__ __forceinline__ void ldmatrix_x2(uint32_t* r, uint32_t addr) {
    asm volatile("ldmatrix.sync.aligned.m8n8.x2.shared.b16 {%0,%1}, [%2];"
                 : "=r"(r[0]), "=r"(r[1]) : "r"(addr));
}
__device__ __forceinline__ void mma16816(float* d, const uint32_t* a, const uint32_t* b) {
    asm volatile("mma.sync.aligned.m16n8k16.row.col.f32.bf16.bf16.f32 "
                 "{%0,%1,%2,%3}, {%4,%5,%6,%7}, {%8,%9}, {%0,%1,%2,%3};"
                 : "+f"(d[0]), "+f"(d[1]), "+f"(d[2]), "+f"(d[3])
                 : "r"(a[0]), "r"(a[1]), "r"(a[2]), "r"(a[3]), "r"(b[0]), "r"(b[1]));
}
__device__ __forceinline__ void cp16(uint32_t dst, const void* src, int sz) {
    asm volatile("cp.async.cg.shared.global [%0], [%1], 16, %2;"
                 :: "r"(dst), "l"(src), "r"(sz));
}
__device__ __forceinline__ void cp16u(uint32_t dst, const void* src) {
    asm volatile("cp.async.cg.shared.global [%0], [%1], 16;"
                 :: "r"(dst), "l"(src));
}
#define CP_COMMIT() asm volatile("cp.async.commit_group;" ::: "memory")
#define CP_WAIT1()  asm volatile("cp.async.wait_group 1;" ::: "memory")

#define AROW 80                     // 32 halves (64B) + 16B pad

// ---------------- ONE setup kernel: extract + wtrans + wtransc + prep ---------
#define WTR_B  ((NBIG / 32) * (D_DIM / 32))   // 864
#define WTRC_B ((HID / 32) * (NL / 32))       // 64

__global__ void __launch_bounds__(256) setup_kernel(
    const float* __restrict__ sent,
    const int* __restrict__ esent,
    const int* __restrict__ estart,
    const int* __restrict__ elen,
    const float* __restrict__ W1,
    const float* __restrict__ Wproj,
    const float* __restrict__ Wself,
    const float* __restrict__ Wintra,
    const float* __restrict__ Winter,
    int E)
{
    int b = blockIdx.x;
    int tid = threadIdx.x;

    if (b < E) {                                  // ---- extract ----
        if (tid < D_DIM / 4) {
            int e = b;
            int len = elen[e] + 1;
            int st  = estart[e];
            int snt = esent[e];
            float inv = 1.0f / (float)len;
            const float4* base = (const float4*)(sent + (size_t)snt * S_LEN * D_DIM);
            int d4 = tid;
            float4 acc = make_float4(0.f, 0.f, 0.f, 0.f);
            for (int o = 0; o < len; o++) {
                int idx = st + o; if (idx > S_LEN - 1) idx = S_LEN - 1;
                float4 v = base[(size_t)idx * (D_DIM / 4) + d4];
                acc.x += v.x; acc.y += v.y; acc.z += v.z; acc.w += v.w;
            }
            acc.x *= inv; acc.y *= inv; acc.z *= inv; acc.w *= inv;
            float vv[4] = {acc.x, acc.y, acc.z, acc.w};
            unsigned short h[4], l[4];
            #pragma unroll
            for (int j = 0; j < 4; j++) {
                __nv_bfloat16 hb = __float2bfloat16_rn(vv[j]);
                __nv_bfloat16 lb = __float2bfloat16_rn(vv[j] - __bfloat162float(hb));
                h[j] = __bfloat16_as_ushort(hb);
                l[j] = __bfloat16_as_ushort(lb);
            }
            ushort4* row = (ushort4*)(g_Acat + (size_t)e * KS);
            row[d4]              = make_ushort4(h[0], h[1], h[2], h[3]);
            row[(768 / 4) + d4]  = make_ushort4(l[0], l[1], l[2], l[3]);
        }
        return;
    }
    b -= E;

    if (b < WTR_B) {                              // ---- wtrans (Bcat) ----
        __shared__ float t[32][33];
        int n0 = (b % (NBIG / 32)) * 32, k0 = (b / (NBIG / 32)) * 32;
        int tx = tid & 31, ty = tid >> 5;
        #pragma unroll
        for (int i = 0; i < 32; i += 8) {
            int k = k0 + ty + i, n = n0 + tx;
            float v;
            if (n < 512)        v = W1[(size_t)k * HID + n];
            else if (n < 1024)  v = W1[(size_t)(768 + k) * HID + (n - 512)];
            else                v = Wproj[(size_t)k * NL + (n - 1024)];
            t[ty + i][tx] = v;
        }
        __syncthreads();
        #pragma unroll
        for (int i = 0; i < 32; i += 8) {
            int n = n0 + ty + i, k = k0 + tx;
            float v = t[tx][ty + i];
            __nv_bfloat16 hb = __float2bfloat16_rn(v);
            __nv_bfloat16 lb = __float2bfloat16_rn(v - __bfloat162float(hb));
            g_Bcat[(size_t)n * KS + k]       = hb;
            g_Bcat[(size_t)n * KS + 768 + k] = lb;
        }
        return;
    }
    b -= WTR_B;

    if (b < WTRC_B) {                             // ---- wtransc (W1cT) ----
        __shared__ float t2[32][33];
        const float* W1c = W1 + (size_t)1536 * HID;
        int n0 = (b % (HID / 32)) * 32, k0 = (b / (HID / 32)) * 32;
        int tx = tid & 31, ty = tid >> 5;
        #pragma unroll
        for (int i = 0; i < 32; i += 8) {
            int k = k0 + ty + i, n = n0 + tx;
            t2[ty + i][tx] = W1c[(size_t)k * HID + n];
        }
        __syncthreads();
        #pragma unroll
        for (int i = 0; i < 32; i += 8) {
            int n = n0 + ty + i, k = k0 + tx;
            float v = t2[tx][ty + i];
            __nv_bfloat16 hb = __float2bfloat16_rn(v);
            __nv_bfloat16 lb = __float2bfloat16_rn(v - __bfloat162float(hb));
            g_W1cT[(size_t)n * KSC + k]       = hb;
            g_W1cT[(size_t)n * KSC + 128 + k] = lb;
        }
        return;
    }
    b -= WTRC_B;

    {                                             // ---- prep ----
        long i = (long)b * 256 + tid;
        const long N_WCAT = 3 * NL * NL;
        if (i < N_WCAT) {
            int k = (int)(i / NL), d = (int)(i % NL);
            const float* src = (k < NL) ? Wself : ((k < 2 * NL) ? Wintra : Winter);
            g_Wcat[i] = src[(k % NL) * NL + d];
            return;
        }
        i -= N_WCAT;
        if (i < (long)E * NL) { g_sintra[0][i] = 0.f; g_sinter[0][i] = 0.f; return; }
        i -= (long)E * NL;
        if (i < E) { g_cintra[0][i] = 0.f; g_cinter[0][i] = 0.f; return; }
        i -= E;
        if (i < 4) g_losspart[i] = 0.f;
    }
}

// ---------------- big mma GEMM: shared-operand bf16x3, 128x128, 3-stage -------
#define BIG_TILE (128 * AROW)               // 10240 per tile
#define BIG_STG  (4 * BIG_TILE)             // 40960 per stage
#define BIG_SMEM (3 * BIG_STG)              // 122880 dynamic

__global__ void __launch_bounds__(256) mma_gemm(
    int E_,
    const __nv_bfloat16* __restrict__ Acat,
    const __nv_bfloat16* __restrict__ Bcat,
    float* __restrict__ Cout,
    __nv_bfloat16* __restrict__ xcat)
{
    extern __shared__ char sm[];
    const int tid  = threadIdx.x;
    const int lane = tid & 31, wid = tid >> 5;
    const int wm = (wid & 1) * 64;
    const int wn = (wid >> 1) * 32;
    const int brow = blockIdx.y * 128;
    const int bcol = blockIdx.x * 128;

    float acc[4][4][4];
    #pragma unroll
    for (int mi = 0; mi < 4; mi++)
        #pragma unroll
        for (int ni = 0; ni < 4; ni++)
            #pragma unroll
            for (int r = 0; r < 4; r++) acc[mi][ni][r] = 0.f;

    auto issue = [&](int c, int s) {
        char* base = sm + s * BIG_STG;
        #pragma unroll
        for (int j = 0; j < 8; j++) {
            int idx  = tid + j * 256;
            int tile = idx >> 9;
            int r    = (idx >> 2) & 127;
            int off  = (idx & 3) * 16;
            uint32_t dst = smem_u32(base + tile * BIG_TILE + r * AROW + off);
            if (tile == 0) {
                int gr = brow + r; int ok = (gr < E_);
                cp16(dst, (const char*)(Acat + (size_t)(ok ? gr : 0) * KS
                                        + (size_t)c * BKH) + off, ok ? 16 : 0);
            } else if (tile == 1) {
                int gr = brow + r; int ok = (gr < E_);
                cp16(dst, (const char*)(Acat + (size_t)(ok ? gr : 0) * KS + 768
                                        + (size_t)c * BKH) + off, ok ? 16 : 0);
            } else if (tile == 2) {
                cp16u(dst, (const char*)(Bcat + (size_t)(bcol + r) * KS
                                         + (size_t)c * BKH) + off);
            } else {
                cp16u(dst, (const char*)(Bcat + (size_t)(bcol + r) * KS + 768
                                         + (size_t)c * BKH) + off);
            }
        }
        CP_COMMIT();
    };

    issue(0, 0);
    issue(1, 1);

    for (int c = 0; c < NCH2; c++) {
        int s = c % 3;
        CP_WAIT1();
        __syncthreads();
        if (c + 2 < NCH2) issue(c + 2, (c + 2) % 3);
        else CP_COMMIT();

        char* base = sm + s * BIG_STG;
        #pragma unroll
        for (int kk = 0; kk < 2; kk++) {
            int aoff = (kk * 16 + (lane >> 4) * 8) * 2;
            int boff = (kk * 16 + ((lane >> 3) & 1) * 8) * 2;
            uint32_t ah[4][4], al[4][4], bh[4][2], bl[4][2];
            #pragma unroll
            for (int mi = 0; mi < 4; mi++) {
                int rr = (wm + mi * 16 + (lane & 15)) * AROW;
                ldmatrix_x4(ah[mi], smem_u32(base + rr + aoff));
                ldmatrix_x4(al[mi], smem_u32(base + BIG_TILE + rr + aoff));
            }
            #pragma unroll
            for (int ni = 0; ni < 4; ni++) {
                int rr = (wn + ni * 8 + (lane & 7)) * AROW;
                ldmatrix_x2(bh[ni], smem_u32(base + 2 * BIG_TILE + rr + boff));
                ldmatrix_x2(bl[ni], smem_u32(base + 3 * BIG_TILE + rr + boff));
            }
            #pragma unroll
            for (int mi = 0; mi < 4; mi++)
                #pragma unroll
                for (int ni = 0; ni < 4; ni++) {
                    mma16816(acc[mi][ni], ah[mi], bh[ni]);
                    mma16816(acc[mi][ni], al[mi], bh[ni]);
                    mma16816(acc[mi][ni], ah[mi], bl[ni]);
                }
        }
    }

    const bool isX = (bcol == 1024);
    #pragma unroll
    for (int mi = 0; mi < 4; mi++) {
        int m0 = brow + wm + mi * 16 + (lane >> 2);
        #pragma unroll
        for (int ni = 0; ni < 4; ni++) {
            int n = bcol + wn + ni * 8 + (lane & 3) * 2;
            #pragma unroll
            for (int half = 0; half < 2; half++) {
                int r = m0 + half * 8;
                if (r >= E_) continue;
                float c0 = acc[mi][ni][half * 2 + 0];
                float c1 = acc[mi][ni][half * 2 + 1];
                *(float2*)(Cout + (size_t)r * NBIG + n) = make_float2(c0, c1);
                if (isX) {
                    int j = n - 1024;
                    __nv_bfloat16 h0 = __float2bfloat16_rn(c0);
                    __nv_bfloat16 l0 = __float2bfloat16_rn(c0 - __bfloat162float(h0));
                    __nv_bfloat16 h1 = __float2bfloat16_rn(c1);
                    __nv_bfloat16 l1 = __float2bfloat16_rn(c1 - __bfloat162float(h1));
                    __nv_bfloat16* xr = xcat + (size_t)r * KSC + j;
                    xr[0] = h0;   xr[1] = h1;
                    xr[128] = l0; xr[129] = l1;
                }
            }
        }
    }
}

// ---------------- cgemm via mma (shared-operand): epi Ap=A0+C+b1, Bp=B0-C -----
#define CG_ATILE (64 * AROW)
#define CG_BTILE (128 * AROW)
#define CG_STG   (2 * CG_ATILE + 2 * CG_BTILE)
#define CG_SMEM  (3 * CG_STG)

__global__ void __launch_bounds__(256) cgemm_mma(
    int E_,
    const __nv_bfloat16* __restrict__ xcat,
    const __nv_bfloat16* __restrict__ W1cT,
    const float* __restrict__ ABX,
    const float* __restrict__ b1,
    float* __restrict__ Ap, float* __restrict__ Bp)
{
    extern __shared__ char sm[];
    const int tid  = threadIdx.x;
    const int lane = tid & 31, wid = tid >> 5;
    const int wm = (wid & 1) * 32;
    const int wn = (wid >> 1) * 32;
    const int brow = blockIdx.y * 64;
    const int bcol = blockIdx.x * 128;

    float acc[2][4][4];
    #pragma unroll
    for (int mi = 0; mi < 2; mi++)
        #pragma unroll
        for (int ni = 0; ni < 4; ni++)
            #pragma unroll
            for (int r = 0; r < 4; r++) acc[mi][ni][r] = 0.f;

    auto issue = [&](int c, int s) {
        char* base = sm + s * CG_STG;
        #pragma unroll
        for (int j = 0; j < 2; j++) {
            int idx  = tid + j * 256;
            int tile = idx >> 8;
            int r    = (idx >> 2) & 63;
            int off  = (idx & 3) * 16;
            int gr = brow + r; int ok = (gr < E_);
            uint32_t dst = smem_u32(base + tile * CG_ATILE + r * AROW + off);
            cp16(dst, (const char*)(xcat + (size_t)(ok ? gr : 0) * KSC
                                    + (tile ? 128 : 0) + (size_t)c * BKH) + off,
                 ok ? 16 : 0);
        }
        #pragma unroll
        for (int j = 0; j < 4; j++) {
            int idx  = tid + j * 256;
            int tile = idx >> 9;
            int r    = (idx >> 2) & 127;
            int off  = (idx & 3) * 16;
            uint32_t dst = smem_u32(base + 2 * CG_ATILE + tile * CG_BTILE + r * AROW + off);
            cp16u(dst, (const char*)(W1cT + (size_t)(bcol + r) * KSC
                                     + (tile ? 128 : 0) + (size_t)c * BKH) + off);
        }
        CP_COMMIT();
    };

    issue(0, 0);
    issue(1, 1);

    for (int c = 0; c < NCHC2; c++) {
        int s = c % 3;
        CP_WAIT1();
        __syncthreads();
        if (c + 2 < NCHC2) issue(c + 2, (c + 2) % 3);
        else CP_COMMIT();

        char* base = sm + s * CG_STG;
        #pragma unroll
        for (int kk = 0; kk < 2; kk++) {
            int aoff = (kk * 16 + (lane >> 4) * 8) * 2;
            int boff = (kk * 16 + ((lane >> 3) & 1) * 8) * 2;
            uint32_t ah[2][4], al[2][4], bh[4][2], bl[4][2];
            #pragma unroll
            for (int mi = 0; mi < 2; mi++) {
                int rr = (wm + mi * 16 + (lane & 15)) * AROW;
                ldmatrix_x4(ah[mi], smem_u32(base + rr + aoff));
                ldmatrix_x4(al[mi], smem_u32(base + CG_ATILE + rr + aoff));
            }
            #pragma unroll
            for (int ni = 0; ni < 4; ni++) {
                int rr = (wn + ni * 8 + (lane & 7)) * AROW;
                ldmatrix_x2(bh[ni], smem_u32(base + 2 * CG_ATILE + rr + boff));
                ldmatrix_x2(bl[ni], smem_u32(base + 2 * CG_ATILE + CG_BTILE + rr + boff));
            }
            #pragma unroll
            for (int mi = 0; mi < 2; mi++)
                #pragma unroll
                for (int ni = 0; ni < 4; ni++) {
                    mma16816(acc[mi][ni], ah[mi], bh[ni]);
                    mma16816(acc[mi][ni], al[mi], bh[ni]);
                    mma16816(acc[mi][ni], ah[mi], bl[ni]);
                }
        }
    }

    #pragma unroll
    for (int mi = 0; mi < 2; mi++) {
        int m0 = brow + wm + mi * 16 + (lane >> 2);
        #pragma unroll
        for (int ni = 0; ni < 4; ni++) {
            int n = bcol + wn + ni * 8 + (lane & 3) * 2;
            float2 b1v = *(const float2*)(b1 + n);
            #pragma unroll
            for (int half = 0; half < 2; half++) {
                int r = m0 + half * 8;
                if (r >= E_) continue;
                float c0 = acc[mi][ni][half * 2 + 0];
                float c1 = acc[mi][ni][half * 2 + 1];
                float2 a0v = *(const float2*)(ABX + (size_t)r * NBIG + n);
                float2 b0v = *(const float2*)(ABX + (size_t)r * NBIG + 512 + n);
                *(float2*)(Ap + (size_t)r * HID + n) =
                    make_float2(a0v.x + c0 + b1v.x, a0v.y + c1 + b1v.y);
                *(float2*)(Bp + (size_t)r * HID + n) =
                    make_float2(b0v.x - c0, b0v.y - c1);
            }
        }
    }
}

// ---------------- fused update GEMM: x_out = relu(Z@Wcat); writes xout + xcat -
__device__ __forceinline__ float4 z_load(
    const float* __restrict__ xin, int xld,
    const float* __restrict__ sintra, const float* __restrict__ sinter,
    const float* __restrict__ cintra, const float* __restrict__ cinter,
    int r, int kg)
{
    int seg = kg >> 7, d = kg & 127;
    if (seg == 0) {
        return *(const float4*)(xin + (size_t)r * xld + d);
    } else if (seg == 1) {
        float4 s = *(const float4*)(sintra + (size_t)r * NL + d);
        float4 xv = *(const float4*)(xin + (size_t)r * xld + d);
        float rc = 0.7f / (cintra[r] + 1.0f);
        return make_float4((s.x + xv.x) * rc, (s.y + xv.y) * rc,
                           (s.z + xv.z) * rc, (s.w + xv.w) * rc);
    } else {
        float4 s = *(const float4*)(sinter + (size_t)r * NL + d);
        float rc = 0.3f / fmaxf(cinter[r], 1.0f);
        return make_float4(s.x * rc, s.y * rc, s.z * rc, s.w * rc);
    }
}

__global__ void __launch_bounds__(256) upd_fused(
    int M,
    const float* __restrict__ xin, int xld,
    const float* __restrict__ sintra, const float* __restrict__ sinter,
    const float* __restrict__ cintra, const float* __restrict__ cinter,
    const float* __restrict__ Wcat,
    float* __restrict__ xout,
    __nv_bfloat16* __restrict__ xcat)
{
    const int BM = 64, BN = 64, BK = 16, KTOT = 3 * NL;
    __shared__ float As[2][BK][BM];
    __shared__ float Bs[2][BK][BN];
    const int tid  = threadIdx.x;
    const int brow = blockIdx.y * BM;
    const int bcol = blockIdx.x * BN;
    const int ar = tid >> 2, ac = (tid & 3) * 4;
    const int br = tid >> 4, bc = (tid & 15) * 4;
    const int tx = tid & 15, ty = tid >> 4;

    float4 areg = make_float4(0.f,0.f,0.f,0.f), breg;
    if (brow + ar < M) areg = z_load(xin, xld, sintra, sinter, cintra, cinter, brow + ar, ac);
    breg = *(const float4*)(Wcat + (size_t)br * NL + bcol + bc);
    As[0][ac+0][ar] = areg.x; As[0][ac+1][ar] = areg.y; As[0][ac+2][ar] = areg.z; As[0][ac+3][ar] = areg.w;
    *(float4*)&Bs[0][br][bc] = breg;
    __syncthreads();

    float acc[4][4];
    #pragma unroll
    for (int i = 0; i < 4; i++)
        #pragma unroll
        for (int j = 0; j < 4; j++) acc[i][j] = 0.f;

    int buf = 0;
    for (int k0 = BK; k0 < KTOT; k0 += BK) {
        areg = make_float4(0.f,0.f,0.f,0.f);
        if (brow + ar < M) areg = z_load(xin, xld, sintra, sinter, cintra, cinter, brow + ar, k0 + ac);
        breg = *(const float4*)(Wcat + (size_t)(k0 + br) * NL + bcol + bc);
        #pragma unroll
        for (int k = 0; k < BK; k++) {
            float av[4], bv[4];
            *(float4*)av = *(const float4*)&As[buf][k][ty * 4];
            *(float4*)bv = *(const float4*)&Bs[buf][k][tx * 4];
            #pragma unroll
            for (int i = 0; i < 4; i++)
                #pragma unroll
                for (int j = 0; j < 4; j++)
                    acc[i][j] = fmaf(av[i], bv[j], acc[i][j]);
        }
        int nb = buf ^ 1;
        As[nb][ac+0][ar] = areg.x; As[nb][ac+1][ar] = areg.y; As[nb][ac+2][ar] = areg.z; As[nb][ac+3][ar] = areg.w;
        *(float4*)&Bs[nb][br][bc] = breg;
        __syncthreads();
        buf = nb;
    }
    #pragma unroll
    for (int k = 0; k < BK; k++) {
        float av[4], bv[4];
        *(float4*)av = *(const float4*)&As[buf][k][ty * 4];
        *(float4*)bv = *(const float4*)&Bs[buf][k][tx * 4];
        #pragma unroll
        for (int i = 0; i < 4; i++)
            #pragma unroll
            for (int j = 0; j < 4; j++)
                acc[i][j] = fmaf(av[i], bv[j], acc[i][j]);
    }

    #pragma unroll
    for (int i = 0; i < 4; i++) {
        int r = brow + ty * 4 + i;
        if (r >= M) continue;
        float o[4];
        o[0] = fmaxf(acc[i][0], 0.f); o[1] = fmaxf(acc[i][1], 0.f);
        o[2] = fmaxf(acc[i][2], 0.f); o[3] = fmaxf(acc[i][3], 0.f);
        int col = bcol + tx * 4;
        *(float4*)(xout + (size_t)r * NL + col) = make_float4(o[0], o[1], o[2], o[3]);
        unsigned short hh[4], ll[4];
        #pragma unroll
        for (int j = 0; j < 4; j++) {
            __nv_bfloat16 hb = __float2bfloat16_rn(o[j]);
            __nv_bfloat16 lb = __float2bfloat16_rn(o[j] - __bfloat162float(hb));
            hh[j] = __bfloat16_as_ushort(hb);
            ll[j] = __bfloat16_as_ushort(lb);
        }
        __nv_bfloat16* xr = xcat + (size_t)r * KSC;
        *(ushort4*)(xr + col)       = make_ushort4(hh[0], hh[1], hh[2], hh[3]);
        *(ushort4*)(xr + 128 + col) = make_ushort4(ll[0], ll[1], ll[2], ll[3]);
    }
}

// ---------------- per-pair: 32 pairs/block, double-buffered register loads ----
__global__ void __launch_bounds__(256) pair_kernel(
    const float* __restrict__ Ap, const float* __restrict__ Bp,
    const float* __restrict__ xin, int xld,
    const float* __restrict__ W2, const float* __restrict__ b2,
    const int* __restrict__ pair1, const int* __restrict__ pair2,
    const int* __restrict__ rtype, const int* __restrict__ targ,
    float* sintra, float* sinter, float* cintra, float* cinter,
    float* si_o, float* se_o, float* ci_o, float* ce_o,
    float* lossacc, float* logits_out, int P, int E)
{
    __shared__ float W2s0[HID], W2s1[HID], W2s2[HID];
    __shared__ float b2s[CLS];
    __shared__ float ce_s[8];
    int tid = threadIdx.x;
    for (int i = tid; i < HID; i += 256) {
        W2s0[i] = W2[i * 3 + 0];
        W2s1[i] = W2[i * 3 + 1];
        W2s2[i] = W2[i * 3 + 2];
    }
    if (tid < CLS) b2s[tid] = b2[tid];

    {
        long idx = (long)blockIdx.x * 256 + tid;
        long stride = (long)gridDim.x * 256;
        for (long i = idx; i < (long)E * NL; i += stride) { si_o[i] = 0.f; se_o[i] = 0.f; }
        for (long i = idx; i < E; i += stride) { ci_o[i] = 0.f; ce_o[i] = 0.f; }
    }
    __syncthreads();

    int warp = tid >> 5, lane = tid & 31;
    int pbase = blockIdx.x * 32 + warp * 4;
    float ce_sum = 0.f;

    float4 dbuf[2][8];                    // [buffer][4x a-half, 4x b-half]
    int pp1[2], pp2[2];
    bool valid[2];

    auto load_pair = [&](int s, int p) {
        valid[s] = (p < P);
        if (!valid[s]) return;
        int p1 = pair1[p], p2 = pair2[p];
        pp1[s] = p1; pp2[s] = p2;
        const float4* a4 = (const float4*)(Ap + (size_t)p1 * HID);
        const float4* b4 = (const float4*)(Bp + (size_t)p2 * HID);
        #pragma unroll
        for (int j = 0; j < 4; j++) {
            dbuf[s][j]     = a4[j * 32 + lane];
            dbuf[s][4 + j] = b4[j * 32 + lane];
        }
    };

    load_pair(0, pbase);

    #pragma unroll
    for (int sub = 0; sub < 4; sub++) {
        int cb = sub & 1, nb = cb ^ 1;
        if (sub + 1 < 4) load_pair(nb, pbase + sub + 1);

        if (valid[cb]) {
            int p  = pbase + sub;
            int p1 = pp1[cb], p2 = pp2[cb];
            float a0 = 0.f, a1 = 0.f, a2 = 0.f;
            #pragma unroll
            for (int j = 0; j < 4; j++) {
                float4 av = dbuf[cb][j], bv = dbuf[cb][4 + j];
                float4 h;
                h.x = fmaxf(av.x + bv.x, 0.f);
                h.y = fmaxf(av.y + bv.y, 0.f);
                h.z = fmaxf(av.z + bv.z, 0.f);
                h.w = fmaxf(av.w + bv.w, 0.f);
                int base = (j * 32 + lane) * 4;
                float4 w0 = *(const float4*)&W2s0[base];
                float4 w1 = *(const float4*)&W2s1[base];
                float4 w2 = *(const float4*)&W2s2[base];
                a0 = fmaf(h.x, w0.x, fmaf(h.y, w0.y, fmaf(h.z, w0.z, fmaf(h.w, w0.w, a0))));
                a1 = fmaf(h.x, w1.x, fmaf(h.y, w1.y, fmaf(h.z, w1.z, fmaf(h.w, w1.w, a1))));
                a2 = fmaf(h.x, w2.x, fmaf(h.y, w2.y, fmaf(h.z, w2.z, fmaf(h.w, w2.w, a2))));
            }
            #pragma unroll
            for (int o = 16; o; o >>= 1) {
                a0 += __shfl_xor_sync(0xffffffffu, a0, o);
                a1 += __shfl_xor_sync(0xffffffffu, a1, o);
                a2 += __shfl_xor_sync(0xffffffffu, a2, o);
            }
            float l0 = a0 + b2s[0], l1 = a1 + b2s[1], l2 = a2 + b2s[2];
            float m = fmaxf(l0, fmaxf(l1, l2));
            float s = expf(l0 - m) + expf(l1 - m) + expf(l2 - m);
            int tg = targ[p];
            float lt = (tg == 0) ? l0 : ((tg == 1) ? l1 : l2);
            ce_sum += logf(s) + m - lt;
            if (logits_out != nullptr && lane == 0) {
                logits_out[(size_t)p * 3 + 0] = l0;
                logits_out[(size_t)p * 3 + 1] = l1;
                logits_out[(size_t)p * 3 + 2] = l2;
            }
            int argm = 0; float mm = l0;
            if (l1 > mm) { mm = l1; argm = 1; }
            if (l2 > mm) { mm = l2; argm = 2; }
            bool conf = (1.0f / s) > 0.3f;
            int rt = rtype[p];
            if (conf && (argm == 1 || argm == 2)) {
                bool srcIs1 = (argm == 1);
                int src = srcIs1 ? p1 : p2;
                int dst = srcIs1 ? p2 : p1;
                float* sb = (rt == 0) ? sintra : sinter;
                float* cb2 = (rt == 0) ? cintra : cinter;
                const float* xs = xin + (size_t)src * xld;
                #pragma unroll
                for (int j = 0; j < NL / 32; j++) {
                    int d = j * 32 + lane;
                    atomicAdd(&sb[(size_t)dst * NL + d], xs[d]);
                }
                if (lane == 0) atomicAdd(&cb2[dst], 1.0f);
            }
        }
    }
    if (lane == 0) ce_s[warp] = ce_sum;
    __syncthreads();
    if (tid == 0) {
        float t = ce_s[0] + ce_s[1] + ce_s[2] + ce_s[3]
                + ce_s[4] + ce_s[5] + ce_s[6] + ce_s[7];
        atomicAdd(lossacc, t);
    }
}

__global__ void final_loss_kernel(const float* lp, float* out, int P)
{
    out[0] = (lp[0] + lp[1] * 0.5f + lp[2] * (1.0f / 3.0f)) / (float)P;
}

// ---------------- launch ------------------------------------------------------
extern "C" void kernel_launch(void* const* d_in, const int* in_sizes, int n_in,
                              void* d_out, int out_size)
{
    const float* sent   = (const float*)d_in[0];
    const float* Wproj  = (const float*)d_in[1];
    const float* W1     = (const float*)d_in[2];
    const float* b1     = (const float*)d_in[3];
    const float* W2     = (const float*)d_in[4];
    const float* b2     = (const float*)d_in[5];
    const float* Wself  = (const float*)d_in[6];
    const float* Wintra = (const float*)d_in[7];
    const float* Winter = (const float*)d_in[8];
    const int* esent  = (const int*)d_in[9];
    const int* estart = (const int*)d_in[10];
    const int* elen   = (const int*)d_in[11];
    const int* pair1  = (const int*)d_in[12];
    const int* pair2  = (const int*)d_in[13];
    const int* rtype  = (const int*)d_in[14];
    const int* targ   = (const int*)d_in[15];
    float* out = (float*)d_out;

    int E = in_sizes[9];
    int P = in_sizes[12];
    if (E > E_MAX) E = E_MAX;
    if (P > P_MAX) P = P_MAX;

    __nv_bfloat16 *Acat, *Bcat, *W1cT, *xcat;
    float *ABX, *Ap, *Bp, *lp, *Wcat;
    float *xb[2], *si[2], *se[2], *ci[2], *ce[2];
    cudaGetSymbolAddress((void**)&Acat, g_Acat);
    cudaGetSymbolAddress((void**)&Bcat, g_Bcat);
    cudaGetSymbolAddress((void**)&W1cT, g_W1cT);
    cudaGetSymbolAddress((void**)&xcat, g_xcat);
    cudaGetSymbolAddress((void**)&ABX,  g_ABX);
    cudaGetSymbolAddress((void**)&Ap,   g_Ap);
    cudaGetSymbolAddress((void**)&Bp,   g_Bp);
    cudaGetSymbolAddress((void**)&Wcat, g_Wcat);
    cudaGetSymbolAddress((void**)&lp,   g_losspart);
    {
        float* base;
        cudaGetSymbolAddress((void**)&base, g_xbuf);
        xb[0] = base; xb[1] = base + E_MAX * NL;
        cudaGetSymbolAddress((void**)&base, g_sintra);
        si[0] = base; si[1] = base + E_MAX * NL;
        cudaGetSymbolAddress((void**)&base, g_sinter);
        se[0] = base; se[1] = base + E_MAX * NL;
        cudaGetSymbolAddress((void**)&base, g_cintra);
        ci[0] = base; ci[1] = base + E_MAX;
        cudaGetSymbolAddress((void**)&base, g_cinter);
        ce[0] = base; ce[1] = base + E_MAX;
    }

    int loff = out_size - 3 * P;
    if (loff < 0) loff = 0;
    float* logits_out = out + loff;

    // 1) one setup launch
    {
        int prepb = (int)((3L * NL * NL + (long)E * NL + E + 4 + 255) / 256);
        int total = E + WTR_B + WTRC_B + prepb;
        setup_kernel<<<total, 256>>>(sent, esent, estart, elen,
                                     W1, Wproj, Wself, Wintra, Winter, E);
    }

    // 2) tensor-core big GEMM (also emits xcat for it=0)
    cudaFuncSetAttribute(mma_gemm, cudaFuncAttributeMaxDynamicSharedMemorySize, BIG_SMEM);
    cudaFuncSetAttribute(cgemm_mma, cudaFuncAttributeMaxDynamicSharedMemorySize, CG_SMEM);
    {
        dim3 g(NBIG / 128, (E_MAX + 127) / 128);   // 9 x 16 = 144 CTAs
        mma_gemm<<<g, 256, BIG_SMEM>>>(E, Acat, Bcat, ABX, xcat);
    }

    // 3) three iterations
    for (int it = 0; it < 3; it++) {
        int ph = it & 1, po = ph ^ 1;
        const float* xin = (it == 0) ? (ABX + 1024) : xb[(it - 1) & 1];
        int xld = (it == 0) ? NBIG : NL;
        float* xout = xb[it & 1];

        {
            dim3 g(HID / 128, (E + 63) / 64);     // 4 x 32
            cgemm_mma<<<g, 256, CG_SMEM>>>(E, xcat, W1cT, ABX, b1, Ap, Bp);
        }
        pair_kernel<<<(P + 31) / 32, 256>>>(Ap, Bp, xin, xld, W2, b2,
                                          pair1, pair2, rtype, targ,
                                          si[ph], se[ph], ci[ph], ce[ph],
                                          si[po], se[po], ci[po], ce[po],
                                          lp + it, (it == 2) ? logits_out : nullptr, P, E);
        {
            dim3 g(NL / 64, (E + 63) / 64);
            upd_fused<<<g, 256>>>(E, xin, xld,
                                  si[ph], se[ph], ci[ph], ce[ph],
                                  Wcat, xout, xcat);
        }
    }

    // 4) loss
    final_loss_kernel<<<1, 1>>>(lp, out, P);
}

// round 14
// speedup vs baseline: 1.1420x; 1.1420x over previous
#include <cuda_runtime.h>
#include <cuda_bf16.h>
#include <math.h>
#include <stdint.h>

#define NSENT 64
#define S_LEN 512
#define D_DIM 768
#define NL    128
#define HID   512
#define CLS   3
#define E_MAX 2000
#define P_MAX 20000
#define NBIG  1152            // 512(A0) + 512(B0) + 128(x0)
#define KS    1536            // 2*768: [hi | lo]
#define KSC   256             // 2*128: [hi | lo]
#define BKH   32              // K-halves per chunk
#define NCH2  (D_DIM / BKH)   // 24
#define NCHC2 (NL / BKH)      // 4

// ---------------- static device scratch ----------------
__device__ __nv_bfloat16 g_Acat[E_MAX * KS];     // [hi | lo]
__device__ __nv_bfloat16 g_Bcat[NBIG * KS];      // W^T, [hi | lo]
__device__ __nv_bfloat16 g_W1cT[HID * KSC];      // W1c^T, [hi | lo]
__device__ __nv_bfloat16 g_xcat[E_MAX * KSC];    // x split [hi | lo]
__device__ float g_ABX  [E_MAX * NBIG];          // [A0 | B0 | x0]
__device__ float g_Ap   [E_MAX * HID];           // A0 + C + b1
__device__ float g_Bp   [E_MAX * HID];           // B0 - C
__device__ float g_xbuf [2][E_MAX * NL];
__device__ float g_sintra[2][E_MAX * NL];
__device__ float g_sinter[2][E_MAX * NL];
__device__ float g_cintra[2][E_MAX];
__device__ float g_cinter[2][E_MAX];
__device__ float g_Wcat [3 * NL * NL];
__device__ float g_losspart[4];
__device__ int   g_done;                         // completion counter (it=2)

// ---------------- warp-mma / cp.async helpers ----------------
__device__ __forceinline__ uint32_t smem_u32(const void* p) {
    uint32_t a;
    asm("{ .reg .u64 t; cvta.to.shared.u64 t, %1; cvt.u32.u64 %0, t; }"
        : "=r"(a) : "l"(p));
    return a;
}
__device__ __forceinline__ void ldmatrix_x4(uint32_t* r, uint32_t addr) {
    asm volatile("ldmatrix.sync.aligned.m8n8.x4.shared.b16 {%0,%1,%2,%3}, [%4];"
                 : "=r"(r[0]), "=r"(r[1]), "=r"(r[2]), "=r"(r[3]) : "r"(addr));
}
__device__ __forceinline__ void ldmatrix_x2(uint32_t* r, uint32_t addr) {
    asm volatile("ldmatrix.sync.aligned.m8n8.x2.shared.b16 {%0,%1}, [%2];"
                 : "=r"(r[0]), "=r"(r[1]) : "r"(addr));
}
__device__ __forceinline__ void mma16816(float* d, const uint32_t* a, const uint32_t* b) {
    asm volatile("mma.sync.aligned.m16n8k16.row.col.f32.bf16.bf16.f32 "
                 "{%0,%1,%2,%3}, {%4,%5,%6,%7}, {%8,%9}, {%0,%1,%2,%3};"
                 : "+f"(d[0]), "+f"(d[1]), "+f"(d[2]), "+f"(d[3])
                 : "r"(a[0]), "r"(a[1]), "r"(a[2]), "r"(a[3]), "r"(b[0]), "r"(b[1]));
}
__device__ __forceinline__ void cp16(uint32_t dst, const void* src, int sz) {
    asm volatile("cp.async.cg.shared.global [%0], [%1], 16, %2;"
                 :: "r"(dst), "l"(src), "r"(sz));
}
__device__ __forceinline__ void cp16u(uint32_t dst, const void* src) {
    asm volatile("cp.async.cg.shared.global [%0], [%1], 16;"
                 :: "r"(dst), "l"(src));
}
#define CP_COMMIT() asm volatile("cp.async.commit_group;" ::: "memory")
#define CP_WAIT1()  asm volatile("cp.async.wait_group 1;" ::: "memory")

#define AROW 80                     // 32 halves (64B) + 16B pad

// ---------------- ONE setup kernel: extract + wtrans + wtransc + prep ---------
#define WTR_B  ((NBIG / 32) * (D_DIM / 32))   // 864
#define WTRC_B ((HID / 32) * (NL / 32))       // 64

__global__ void __launch_bounds__(256) setup_kernel(
    const float* __restrict__ sent,
    const int* __restrict__ esent,
    const int* __restrict__ estart,
    const int* __restrict__ elen,
    const float* __restrict__ W1,
    const float* __restrict__ Wproj,
    const float* __restrict__ Wself,
    const float* __restrict__ Wintra,
    const float* __restrict__ Winter,
    int E)
{
    int b = blockIdx.x;
    int tid = threadIdx.x;

    if (b < E) {                                  // ---- extract ----
        if (tid < D_DIM / 4) {
            int e = b;
            int len = elen[e] + 1;
            int st  = estart[e];
            int snt = esent[e];
            float inv = 1.0f / (float)len;
            const float4* base = (const float4*)(sent + (size_t)snt * S_LEN * D_DIM);
            int d4 = tid;
            float4 acc = make_float4(0.f, 0.f, 0.f, 0.f);
            for (int o = 0; o < len; o++) {
                int idx = st + o; if (idx > S_LEN - 1) idx = S_LEN - 1;
                float4 v = base[(size_t)idx * (D_DIM / 4) + d4];
                acc.x += v.x; acc.y += v.y; acc.z += v.z; acc.w += v.w;
            }
            acc.x *= inv; acc.y *= inv; acc.z *= inv; acc.w *= inv;
            float vv[4] = {acc.x, acc.y, acc.z, acc.w};
            unsigned short h[4], l[4];
            #pragma unroll
            for (int j = 0; j < 4; j++) {
                __nv_bfloat16 hb = __float2bfloat16_rn(vv[j]);
                __nv_bfloat16 lb = __float2bfloat16_rn(vv[j] - __bfloat162float(hb));
                h[j] = __bfloat16_as_ushort(hb);
                l[j] = __bfloat16_as_ushort(lb);
            }
            ushort4* row = (ushort4*)(g_Acat + (size_t)e * KS);
            row[d4]              = make_ushort4(h[0], h[1], h[2], h[3]);
            row[(768 / 4) + d4]  = make_ushort4(l[0], l[1], l[2], l[3]);
        }
        return;
    }
    b -= E;

    if (b < WTR_B) {                              // ---- wtrans (Bcat) ----
        __shared__ float t[32][33];
        int n0 = (b % (NBIG / 32)) * 32, k0 = (b / (NBIG / 32)) * 32;
        int tx = tid & 31, ty = tid >> 5;
        #pragma unroll
        for (int i = 0; i < 32; i += 8) {
            int k = k0 + ty + i, n = n0 + tx;
            float v;
            if (n < 512)        v = W1[(size_t)k * HID + n];
            else if (n < 1024)  v = W1[(size_t)(768 + k) * HID + (n - 512)];
            else                v = Wproj[(size_t)k * NL + (n - 1024)];
            t[ty + i][tx] = v;
        }
        __syncthreads();
        #pragma unroll
        for (int i = 0; i < 32; i += 8) {
            int n = n0 + ty + i, k = k0 + tx;
            float v = t[tx][ty + i];
            __nv_bfloat16 hb = __float2bfloat16_rn(v);
            __nv_bfloat16 lb = __float2bfloat16_rn(v - __bfloat162float(hb));
            g_Bcat[(size_t)n * KS + k]       = hb;
            g_Bcat[(size_t)n * KS + 768 + k] = lb;
        }
        return;
    }
    b -= WTR_B;

    if (b < WTRC_B) {                             // ---- wtransc (W1cT) ----
        __shared__ float t2[32][33];
        const float* W1c = W1 + (size_t)1536 * HID;
        int n0 = (b % (HID / 32)) * 32, k0 = (b / (HID / 32)) * 32;
        int tx = tid & 31, ty = tid >> 5;
        #pragma unroll
        for (int i = 0; i < 32; i += 8) {
            int k = k0 + ty + i, n = n0 + tx;
            t2[ty + i][tx] = W1c[(size_t)k * HID + n];
        }
        __syncthreads();
        #pragma unroll
        for (int i = 0; i < 32; i += 8) {
            int n = n0 + ty + i, k = k0 + tx;
            float v = t2[tx][ty + i];
            __nv_bfloat16 hb = __float2bfloat16_rn(v);
            __nv_bfloat16 lb = __float2bfloat16_rn(v - __bfloat162float(hb));
            g_W1cT[(size_t)n * KSC + k]       = hb;
            g_W1cT[(size_t)n * KSC + 128 + k] = lb;
        }
        return;
    }
    b -= WTRC_B;

    {                                             // ---- prep ----
        long i = (long)b * 256 + tid;
        const long N_WCAT = 3 * NL * NL;
        if (i < N_WCAT) {
            int k = (int)(i / NL), d = (int)(i % NL);
            const float* src = (k < NL) ? Wself : ((k < 2 * NL) ? Wintra : Winter);
            g_Wcat[i] = src[(k % NL) * NL + d];
            return;
        }
        i -= N_WCAT;
        if (i < (long)E * NL) { g_sintra[0][i] = 0.f; g_sinter[0][i] = 0.f; return; }
        i -= (long)E * NL;
        if (i < E) { g_cintra[0][i] = 0.f; g_cinter[0][i] = 0.f; return; }
        i -= E;
        if (i < 4) g_losspart[i] = 0.f;
        if (i == 4) g_done = 0;
    }
}

// ---------------- big mma GEMM: shared-operand bf16x3, 128x128, 3-stage -------
#define BIG_TILE (128 * AROW)               // 10240 per tile
#define BIG_STG  (4 * BIG_TILE)             // 40960 per stage
#define BIG_SMEM (3 * BIG_STG)              // 122880 dynamic

__global__ void __launch_bounds__(256) mma_gemm(
    int E_,
    const __nv_bfloat16* __restrict__ Acat,
    const __nv_bfloat16* __restrict__ Bcat,
    float* __restrict__ Cout,
    __nv_bfloat16* __restrict__ xcat)
{
    extern __shared__ char sm[];
    const int tid  = threadIdx.x;
    const int lane = tid & 31, wid = tid >> 5;
    const int wm = (wid & 1) * 64;
    const int wn = (wid >> 1) * 32;
    const int brow = blockIdx.y * 128;
    const int bcol = blockIdx.x * 128;

    float acc[4][4][4];
    #pragma unroll
    for (int mi = 0; mi < 4; mi++)
        #pragma unroll
        for (int ni = 0; ni < 4; ni++)
            #pragma unroll
            for (int r = 0; r < 4; r++) acc[mi][ni][r] = 0.f;

    auto issue = [&](int c, int s) {
        char* base = sm + s * BIG_STG;
        #pragma unroll
        for (int j = 0; j < 8; j++) {
            int idx  = tid + j * 256;
            int tile = idx >> 9;
            int r    = (idx >> 2) & 127;
            int off  = (idx & 3) * 16;
            uint32_t dst = smem_u32(base + tile * BIG_TILE + r * AROW + off);
            if (tile == 0) {
                int gr = brow + r; int ok = (gr < E_);
                cp16(dst, (const char*)(Acat + (size_t)(ok ? gr : 0) * KS
                                        + (size_t)c * BKH) + off, ok ? 16 : 0);
            } else if (tile == 1) {
                int gr = brow + r; int ok = (gr < E_);
                cp16(dst, (const char*)(Acat + (size_t)(ok ? gr : 0) * KS + 768
                                        + (size_t)c * BKH) + off, ok ? 16 : 0);
            } else if (tile == 2) {
                cp16u(dst, (const char*)(Bcat + (size_t)(bcol + r) * KS
                                         + (size_t)c * BKH) + off);
            } else {
                cp16u(dst, (const char*)(Bcat + (size_t)(bcol + r) * KS + 768
                                         + (size_t)c * BKH) + off);
            }
        }
        CP_COMMIT();
    };

    issue(0, 0);
    issue(1, 1);

    for (int c = 0; c < NCH2; c++) {
        int s = c % 3;
        CP_WAIT1();
        __syncthreads();
        if (c + 2 < NCH2) issue(c + 2, (c + 2) % 3);
        else CP_COMMIT();

        char* base = sm + s * BIG_STG;
        #pragma unroll
        for (int kk = 0; kk < 2; kk++) {
            int aoff = (kk * 16 + (lane >> 4) * 8) * 2;
            int boff = (kk * 16 + ((lane >> 3) & 1) * 8) * 2;
            uint32_t ah[4][4], al[4][4], bh[4][2], bl[4][2];
            #pragma unroll
            for (int mi = 0; mi < 4; mi++) {
                int rr = (wm + mi * 16 + (lane & 15)) * AROW;
                ldmatrix_x4(ah[mi], smem_u32(base + rr + aoff));
                ldmatrix_x4(al[mi], smem_u32(base + BIG_TILE + rr + aoff));
            }
            #pragma unroll
            for (int ni = 0; ni < 4; ni++) {
                int rr = (wn + ni * 8 + (lane & 7)) * AROW;
                ldmatrix_x2(bh[ni], smem_u32(base + 2 * BIG_TILE + rr + boff));
                ldmatrix_x2(bl[ni], smem_u32(base + 3 * BIG_TILE + rr + boff));
            }
            #pragma unroll
            for (int mi = 0; mi < 4; mi++)
                #pragma unroll
                for (int ni = 0; ni < 4; ni++) {
                    mma16816(acc[mi][ni], ah[mi], bh[ni]);
                    mma16816(acc[mi][ni], al[mi], bh[ni]);
                    mma16816(acc[mi][ni], ah[mi], bl[ni]);
                }
        }
    }

    const bool isX = (bcol == 1024);
    #pragma unroll
    for (int mi = 0; mi < 4; mi++) {
        int m0 = brow + wm + mi * 16 + (lane >> 2);
        #pragma unroll
        for (int ni = 0; ni < 4; ni++) {
            int n = bcol + wn + ni * 8 + (lane & 3) * 2;
            #pragma unroll
            for (int half = 0; half < 2; half++) {
                int r = m0 + half * 8;
                if (r >= E_) continue;
                float c0 = acc[mi][ni][half * 2 + 0];
                float c1 = acc[mi][ni][half * 2 + 1];
                *(float2*)(Cout + (size_t)r * NBIG + n) = make_float2(c0, c1);
                if (isX) {
                    int j = n - 1024;
                    __nv_bfloat16 h0 = __float2bfloat16_rn(c0);
                    __nv_bfloat16 l0 = __float2bfloat16_rn(c0 - __bfloat162float(h0));
                    __nv_bfloat16 h1 = __float2bfloat16_rn(c1);
                    __nv_bfloat16 l1 = __float2bfloat16_rn(c1 - __bfloat162float(h1));
                    __nv_bfloat16* xr = xcat + (size_t)r * KSC + j;
                    xr[0] = h0;   xr[1] = h1;
                    xr[128] = l0; xr[129] = l1;
                }
            }
        }
    }
}

// ---------------- cgemm via mma (shared-operand): epi Ap=A0+C+b1, Bp=B0-C -----
#define CG_ATILE (64 * AROW)
#define CG_BTILE (128 * AROW)
#define CG_STG   (2 * CG_ATILE + 2 * CG_BTILE)
#define CG_SMEM  (3 * CG_STG)

__global__ void __launch_bounds__(256) cgemm_mma(
    int E_,
    const __nv_bfloat16* __restrict__ xcat,
    const __nv_bfloat16* __restrict__ W1cT,
    const float* __restrict__ ABX,
    const float* __restrict__ b1,
    float* __restrict__ Ap, float* __restrict__ Bp)
{
    extern __shared__ char sm[];
    const int tid  = threadIdx.x;
    const int lane = tid & 31, wid = tid >> 5;
    const int wm = (wid & 1) * 32;
    const int wn = (wid >> 1) * 32;
    const int brow = blockIdx.y * 64;
    const int bcol = blockIdx.x * 128;

    float acc[2][4][4];
    #pragma unroll
    for (int mi = 0; mi < 2; mi++)
        #pragma unroll
        for (int ni = 0; ni < 4; ni++)
            #pragma unroll
            for (int r = 0; r < 4; r++) acc[mi][ni][r] = 0.f;

    auto issue = [&](int c, int s) {
        char* base = sm + s * CG_STG;
        #pragma unroll
        for (int j = 0; j < 2; j++) {
            int idx  = tid + j * 256;
            int tile = idx >> 8;
            int r    = (idx >> 2) & 63;
            int off  = (idx & 3) * 16;
            int gr = brow + r; int ok = (gr < E_);
            uint32_t dst = smem_u32(base + tile * CG_ATILE + r * AROW + off);
            cp16(dst, (const char*)(xcat + (size_t)(ok ? gr : 0) * KSC
                                    + (tile ? 128 : 0) + (size_t)c * BKH) + off,
                 ok ? 16 : 0);
        }
        #pragma unroll
        for (int j = 0; j < 4; j++) {
            int idx  = tid + j * 256;
            int tile = idx >> 9;
            int r    = (idx >> 2) & 127;
            int off  = (idx & 3) * 16;
            uint32_t dst = smem_u32(base + 2 * CG_ATILE + tile * CG_BTILE + r * AROW + off);
            cp16u(dst, (const char*)(W1cT + (size_t)(bcol + r) * KSC
                                     + (tile ? 128 : 0) + (size_t)c * BKH) + off);
        }
        CP_COMMIT();
    };

    issue(0, 0);
    issue(1, 1);

    for (int c = 0; c < NCHC2; c++) {
        int s = c % 3;
        CP_WAIT1();
        __syncthreads();
        if (c + 2 < NCHC2) issue(c + 2, (c + 2) % 3);
        else CP_COMMIT();

        char* base = sm + s * CG_STG;
        #pragma unroll
        for (int kk = 0; kk < 2; kk++) {
            int aoff = (kk * 16 + (lane >> 4) * 8) * 2;
            int boff = (kk * 16 + ((lane >> 3) & 1) * 8) * 2;
            uint32_t ah[2][4], al[2][4], bh[4][2], bl[4][2];
            #pragma unroll
            for (int mi = 0; mi < 2; mi++) {
                int rr = (wm + mi * 16 + (lane & 15)) * AROW;
                ldmatrix_x4(ah[mi], smem_u32(base + rr + aoff));
                ldmatrix_x4(al[mi], smem_u32(base + CG_ATILE + rr + aoff));
            }
            #pragma unroll
            for (int ni = 0; ni < 4; ni++) {
                int rr = (wn + ni * 8 + (lane & 7)) * AROW;
                ldmatrix_x2(bh[ni], smem_u32(base + 2 * CG_ATILE + rr + boff));
                ldmatrix_x2(bl[ni], smem_u32(base + 2 * CG_ATILE + CG_BTILE + rr + boff));
            }
            #pragma unroll
            for (int mi = 0; mi < 2; mi++)
                #pragma unroll
                for (int ni = 0; ni < 4; ni++) {
                    mma16816(acc[mi][ni], ah[mi], bh[ni]);
                    mma16816(acc[mi][ni], al[mi], bh[ni]);
                    mma16816(acc[mi][ni], ah[mi], bl[ni]);
                }
        }
    }

    #pragma unroll
    for (int mi = 0; mi < 2; mi++) {
        int m0 = brow + wm + mi * 16 + (lane >> 2);
        #pragma unroll
        for (int ni = 0; ni < 4; ni++) {
            int n = bcol + wn + ni * 8 + (lane & 3) * 2;
            float2 b1v = *(const float2*)(b1 + n);
            #pragma unroll
            for (int half = 0; half < 2; half++) {
                int r = m0 + half * 8;
                if (r >= E_) continue;
                float c0 = acc[mi][ni][half * 2 + 0];
                float c1 = acc[mi][ni][half * 2 + 1];
                float2 a0v = *(const float2*)(ABX + (size_t)r * NBIG + n);
                float2 b0v = *(const float2*)(ABX + (size_t)r * NBIG + 512 + n);
                *(float2*)(Ap + (size_t)r * HID + n) =
                    make_float2(a0v.x + c0 + b1v.x, a0v.y + c1 + b1v.y);
                *(float2*)(Bp + (size_t)r * HID + n) =
                    make_float2(b0v.x - c0, b0v.y - c1);
            }
        }
    }
}

// ---------------- fused update GEMM: x_out = relu(Z@Wcat); writes xout + xcat -
__device__ __forceinline__ float4 z_load(
    const float* __restrict__ xin, int xld,
    const float* __restrict__ sintra, const float* __restrict__ sinter,
    const float* __restrict__ cintra, const float* __restrict__ cinter,
    int r, int kg)
{
    int seg = kg >> 7, d = kg & 127;
    if (seg == 0) {
        return *(const float4*)(xin + (size_t)r * xld + d);
    } else if (seg == 1) {
        float4 s = *(const float4*)(sintra + (size_t)r * NL + d);
        float4 xv = *(const float4*)(xin + (size_t)r * xld + d);
        float rc = 0.7f / (cintra[r] + 1.0f);
        return make_float4((s.x + xv.x) * rc, (s.y + xv.y) * rc,
                           (s.z + xv.z) * rc, (s.w + xv.w) * rc);
    } else {
        float4 s = *(const float4*)(sinter + (size_t)r * NL + d);
        float rc = 0.3f / fmaxf(cinter[r], 1.0f);
        return make_float4(s.x * rc, s.y * rc, s.z * rc, s.w * rc);
    }
}

__global__ void __launch_bounds__(256) upd_fused(
    int M,
    const float* __restrict__ xin, int xld,
    const float* __restrict__ sintra, const float* __restrict__ sinter,
    const float* __restrict__ cintra, const float* __restrict__ cinter,
    const float* __restrict__ Wcat,
    float* __restrict__ xout,
    __nv_bfloat16* __restrict__ xcat)
{
    const int BM = 64, BN = 64, BK = 16, KTOT = 3 * NL;
    __shared__ float As[2][BK][BM];
    __shared__ float Bs[2][BK][BN];
    const int tid  = threadIdx.x;
    const int brow = blockIdx.y * BM;
    const int bcol = blockIdx.x * BN;
    const int ar = tid >> 2, ac = (tid & 3) * 4;
    const int br = tid >> 4, bc = (tid & 15) * 4;
    const int tx = tid & 15, ty = tid >> 4;

    float4 areg = make_float4(0.f,0.f,0.f,0.f), breg;
    if (brow + ar < M) areg = z_load(xin, xld, sintra, sinter, cintra, cinter, brow + ar, ac);
    breg = *(const float4*)(Wcat + (size_t)br * NL + bcol + bc);
    As[0][ac+0][ar] = areg.x; As[0][ac+1][ar] = areg.y; As[0][ac+2][ar] = areg.z; As[0][ac+3][ar] = areg.w;
    *(float4*)&Bs[0][br][bc] = breg;
    __syncthreads();

    float acc[4][4];
    #pragma unroll
    for (int i = 0; i < 4; i++)
        #pragma unroll
        for (int j = 0; j < 4; j++) acc[i][j] = 0.f;

    int buf = 0;
    for (int k0 = BK; k0 < KTOT; k0 += BK) {
        areg = make_float4(0.f,0.f,0.f,0.f);
        if (brow + ar < M) areg = z_load(xin, xld, sintra, sinter, cintra, cinter, brow + ar, k0 + ac);
        breg = *(const float4*)(Wcat + (size_t)(k0 + br) * NL + bcol + bc);
        #pragma unroll
        for (int k = 0; k < BK; k++) {
            float av[4], bv[4];
            *(float4*)av = *(const float4*)&As[buf][k][ty * 4];
            *(float4*)bv = *(const float4*)&Bs[buf][k][tx * 4];
            #pragma unroll
            for (int i = 0; i < 4; i++)
                #pragma unroll
                for (int j = 0; j < 4; j++)
                    acc[i][j] = fmaf(av[i], bv[j], acc[i][j]);
        }
        int nb = buf ^ 1;
        As[nb][ac+0][ar] = areg.x; As[nb][ac+1][ar] = areg.y; As[nb][ac+2][ar] = areg.z; As[nb][ac+3][ar] = areg.w;
        *(float4*)&Bs[nb][br][bc] = breg;
        __syncthreads();
        buf = nb;
    }
    #pragma unroll
    for (int k = 0; k < BK; k++) {
        float av[4], bv[4];
        *(float4*)av = *(const float4*)&As[buf][k][ty * 4];
        *(float4*)bv = *(const float4*)&Bs[buf][k][tx * 4];
        #pragma unroll
        for (int i = 0; i < 4; i++)
            #pragma unroll
            for (int j = 0; j < 4; j++)
                acc[i][j] = fmaf(av[i], bv[j], acc[i][j]);
    }

    #pragma unroll
    for (int i = 0; i < 4; i++) {
        int r = brow + ty * 4 + i;
        if (r >= M) continue;
        float o[4];
        o[0] = fmaxf(acc[i][0], 0.f); o[1] = fmaxf(acc[i][1], 0.f);
        o[2] = fmaxf(acc[i][2], 0.f); o[3] = fmaxf(acc[i][3], 0.f);
        int col = bcol + tx * 4;
        *(float4*)(xout + (size_t)r * NL + col) = make_float4(o[0], o[1], o[2], o[3]);
        unsigned short hh[4], ll[4];
        #pragma unroll
        for (int j = 0; j < 4; j++) {
            __nv_bfloat16 hb = __float2bfloat16_rn(o[j]);
            __nv_bfloat16 lb = __float2bfloat16_rn(o[j] - __bfloat162float(hb));
            hh[j] = __bfloat16_as_ushort(hb);
            ll[j] = __bfloat16_as_ushort(lb);
        }
        __nv_bfloat16* xr = xcat + (size_t)r * KSC;
        *(ushort4*)(xr + col)       = make_ushort4(hh[0], hh[1], hh[2], hh[3]);
        *(ushort4*)(xr + 128 + col) = make_ushort4(ll[0], ll[1], ll[2], ll[3]);
    }
}

// ---------------- per-pair: 512 thr, 64 pairs/block (4 per warp) --------------
__global__ void __launch_bounds__(512) pair_kernel(
    const float* __restrict__ Ap, const float* __restrict__ Bp,
    const float* __restrict__ xin, int xld,
    const float* __restrict__ W2, const float* __restrict__ b2,
    const int* __restrict__ pair1, const int* __restrict__ pair2,
    const int* __restrict__ rtype, const int* __restrict__ targ,
    float* sintra, float* sinter, float* cintra, float* cinter,
    float* si_o, float* se_o, float* ci_o, float* ce_o,
    float* lossacc, float* logits_out,
    const float* lp_base, float* loss_out, int isLast,
    int P, int E)
{
    __shared__ float W2s0[HID], W2s1[HID], W2s2[HID];
    __shared__ float b2s[CLS];
    __shared__ float ce_s[16];
    int tid = threadIdx.x;
    for (int i = tid; i < HID; i += 512) {
        W2s0[i] = W2[i * 3 + 0];
        W2s1[i] = W2[i * 3 + 1];
        W2s2[i] = W2[i * 3 + 2];
    }
    if (tid < CLS) b2s[tid] = b2[tid];

    {
        long idx = (long)blockIdx.x * 512 + tid;
        long stride = (long)gridDim.x * 512;
        for (long i = idx; i < (long)E * NL; i += stride) { si_o[i] = 0.f; se_o[i] = 0.f; }
        for (long i = idx; i < E; i += stride) { ci_o[i] = 0.f; ce_o[i] = 0.f; }
    }
    __syncthreads();

    int warp = tid >> 5, lane = tid & 31;
    float ce_sum = 0.f;
    #pragma unroll
    for (int sub = 0; sub < 4; sub++) {
        int p = blockIdx.x * 64 + warp * 4 + sub;
        if (p >= P) continue;
        int p1 = pair1[p], p2 = pair2[p];
        const float4* a4 = (const float4*)(Ap + (size_t)p1 * HID);
        const float4* b4 = (const float4*)(Bp + (size_t)p2 * HID);
        float a0 = 0.f, a1 = 0.f, a2 = 0.f;
        #pragma unroll
        for (int j = 0; j < 4; j++) {
            int i4 = j * 32 + lane;
            float4 av = a4[i4], bv = b4[i4];
            float4 h;
            h.x = fmaxf(av.x + bv.x, 0.f);
            h.y = fmaxf(av.y + bv.y, 0.f);
            h.z = fmaxf(av.z + bv.z, 0.f);
            h.w = fmaxf(av.w + bv.w, 0.f);
            int base = i4 * 4;
            float4 w0 = *(const float4*)&W2s0[base];
            float4 w1 = *(const float4*)&W2s1[base];
            float4 w2 = *(const float4*)&W2s2[base];
            a0 = fmaf(h.x, w0.x, fmaf(h.y, w0.y, fmaf(h.z, w0.z, fmaf(h.w, w0.w, a0))));
            a1 = fmaf(h.x, w1.x, fmaf(h.y, w1.y, fmaf(h.z, w1.z, fmaf(h.w, w1.w, a1))));
            a2 = fmaf(h.x, w2.x, fmaf(h.y, w2.y, fmaf(h.z, w2.z, fmaf(h.w, w2.w, a2))));
        }
        #pragma unroll
        for (int o = 16; o; o >>= 1) {
            a0 += __shfl_xor_sync(0xffffffffu, a0, o);
            a1 += __shfl_xor_sync(0xffffffffu, a1, o);
            a2 += __shfl_xor_sync(0xffffffffu, a2, o);
        }
        float l0 = a0 + b2s[0], l1 = a1 + b2s[1], l2 = a2 + b2s[2];
        float m = fmaxf(l0, fmaxf(l1, l2));
        float s = expf(l0 - m) + expf(l1 - m) + expf(l2 - m);
        int tg = targ[p];
        float lt = (tg == 0) ? l0 : ((tg == 1) ? l1 : l2);
        ce_sum += logf(s) + m - lt;
        if (logits_out != nullptr && lane == 0) {
            logits_out[(size_t)p * 3 + 0] = l0;
            logits_out[(size_t)p * 3 + 1] = l1;
            logits_out[(size_t)p * 3 + 2] = l2;
        }
        int argm = 0; float mm = l0;
        if (l1 > mm) { mm = l1; argm = 1; }
        if (l2 > mm) { mm = l2; argm = 2; }
        bool conf = (1.0f / s) > 0.3f;
        int rt = rtype[p];
        if (conf && (argm == 1 || argm == 2)) {
            bool srcIs1 = (argm == 1);
            int src = srcIs1 ? p1 : p2;
            int dst = srcIs1 ? p2 : p1;
            float* sb = (rt == 0) ? sintra : sinter;
            float* cb = (rt == 0) ? cintra : cinter;
            const float* xs = xin + (size_t)src * xld;
            #pragma unroll
            for (int j = 0; j < NL / 32; j++) {
                int d = j * 32 + lane;
                atomicAdd(&sb[(size_t)dst * NL + d], xs[d]);
            }
            if (lane == 0) atomicAdd(&cb[dst], 1.0f);
        }
    }
    if (lane == 0) ce_s[warp] = ce_sum;
    __syncthreads();
    if (tid == 0) {
        float t = 0.f;
        #pragma unroll
        for (int w = 0; w < 16; w++) t += ce_s[w];
        atomicAdd(lossacc, t);
        if (isLast) {
            __threadfence();
            int v = atomicAdd(&g_done, 1);
            if (v == (int)gridDim.x - 1) {
                volatile const float* lv = lp_base;
                loss_out[0] = (lv[0] + lv[1] * 0.5f + lv[2] * (1.0f / 3.0f)) / (float)P;
            }
        }
    }
}

// ---------------- launch ------------------------------------------------------
extern "C" void kernel_launch(void* const* d_in, const int* in_sizes, int n_in,
                              void* d_out, int out_size)
{
    const float* sent   = (const float*)d_in[0];
    const float* Wproj  = (const float*)d_in[1];
    const float* W1     = (const float*)d_in[2];
    const float* b1     = (const float*)d_in[3];
    const float* W2     = (const float*)d_in[4];
    const float* b2     = (const float*)d_in[5];
    const float* Wself  = (const float*)d_in[6];
    const float* Wintra = (const float*)d_in[7];
    const float* Winter = (const float*)d_in[8];
    const int* esent  = (const int*)d_in[9];
    const int* estart = (const int*)d_in[10];
    const int* elen   = (const int*)d_in[11];
    const int* pair1  = (const int*)d_in[12];
    const int* pair2  = (const int*)d_in[13];
    const int* rtype  = (const int*)d_in[14];
    const int* targ   = (const int*)d_in[15];
    float* out = (float*)d_out;

    int E = in_sizes[9];
    int P = in_sizes[12];
    if (E > E_MAX) E = E_MAX;
    if (P > P_MAX) P = P_MAX;

    __nv_bfloat16 *Acat, *Bcat, *W1cT, *xcat;
    float *ABX, *Ap, *Bp, *lp, *Wcat;
    float *xb[2], *si[2], *se[2], *ci[2], *ce[2];
    cudaGetSymbolAddress((void**)&Acat, g_Acat);
    cudaGetSymbolAddress((void**)&Bcat, g_Bcat);
    cudaGetSymbolAddress((void**)&W1cT, g_W1cT);
    cudaGetSymbolAddress((void**)&xcat, g_xcat);
    cudaGetSymbolAddress((void**)&ABX,  g_ABX);
    cudaGetSymbolAddress((void**)&Ap,   g_Ap);
    cudaGetSymbolAddress((void**)&Bp,   g_Bp);
    cudaGetSymbolAddress((void**)&Wcat, g_Wcat);
    cudaGetSymbolAddress((void**)&lp,   g_losspart);
    {
        float* base;
        cudaGetSymbolAddress((void**)&base, g_xbuf);
        xb[0] = base; xb[1] = base + E_MAX * NL;
        cudaGetSymbolAddress((void**)&base, g_sintra);
        si[0] = base; si[1] = base + E_MAX * NL;
        cudaGetSymbolAddress((void**)&base, g_sinter);
        se[0] = base; se[1] = base + E_MAX * NL;
        cudaGetSymbolAddress((void**)&base, g_cintra);
        ci[0] = base; ci[1] = base + E_MAX;
        cudaGetSymbolAddress((void**)&base, g_cinter);
        ce[0] = base; ce[1] = base + E_MAX;
    }

    int loff = out_size - 3 * P;
    if (loff < 0) loff = 0;
    float* logits_out = out + loff;

    // 1) one setup launch (also resets g_done)
    {
        int prepb = (int)((3L * NL * NL + (long)E * NL + E + 4 + 1 + 255) / 256);
        int total = E + WTR_B + WTRC_B + prepb;
        setup_kernel<<<total, 256>>>(sent, esent, estart, elen,
                                     W1, Wproj, Wself, Wintra, Winter, E);
    }

    // 2) tensor-core big GEMM (also emits xcat for it=0)
    cudaFuncSetAttribute(mma_gemm, cudaFuncAttributeMaxDynamicSharedMemorySize, BIG_SMEM);
    cudaFuncSetAttribute(cgemm_mma, cudaFuncAttributeMaxDynamicSharedMemorySize, CG_SMEM);
    {
        dim3 g(NBIG / 128, (E_MAX + 127) / 128);   // 9 x 16 = 144 CTAs
        mma_gemm<<<g, 256, BIG_SMEM>>>(E, Acat, Bcat, ABX, xcat);
    }

    // 3) three iterations
    for (int it = 0; it < 3; it++) {
        int ph = it & 1, po = ph ^ 1;
        const float* xin = (it == 0) ? (ABX + 1024) : xb[(it - 1) & 1];
        int xld = (it == 0) ? NBIG : NL;
        float* xout = xb[it & 1];

        {
            dim3 g(HID / 128, (E + 63) / 64);     // 4 x 32
            cgemm_mma<<<g, 256, CG_SMEM>>>(E, xcat, W1cT, ABX, b1, Ap, Bp);
        }
        pair_kernel<<<(P + 63) / 64, 512>>>(Ap, Bp, xin, xld, W2, b2,
                                          pair1, pair2, rtype, targ,
                                          si[ph], se[ph], ci[ph], ce[ph],
                                          si[po], se[po], ci[po], ce[po],
                                          lp + it, (it == 2) ? logits_out : nullptr,
                                          lp, out, (it == 2) ? 1 : 0, P, E);
        if (it < 2) {
            dim3 g(NL / 64, (E + 63) / 64);
            upd_fused<<<g, 256>>>(E, xin, xld,
                                  si[ph], se[ph], ci[ph], ce[ph],
                                  Wcat, xout, xcat);
        }
    }
}

// round 15
// speedup vs baseline: 1.2159x; 1.0647x over previous
#include <cuda_runtime.h>
#include <cuda_bf16.h>
#include <math.h>
#include <stdint.h>

#define NSENT 64
#define S_LEN 512
#define D_DIM 768
#define NL    128
#define HID   512
#define CLS   3
#define E_MAX 2000
#define P_MAX 20000
#define NBIG  1152            // 512(A0) + 512(B0) + 128(x0)
#define KS    1536            // 2*768: [hi | lo]
#define KSC   256             // 2*128: [hi | lo]
#define BKH   32              // K-halves per chunk
#define NCH2  (D_DIM / BKH)   // 24
#define NCHC2 (NL / BKH)      // 4

// ---------------- static device scratch ----------------
__device__ __nv_bfloat16 g_Acat[E_MAX * KS];     // [hi | lo]
__device__ __nv_bfloat16 g_Bcat[NBIG * KS];      // W^T, [hi | lo]
__device__ __nv_bfloat16 g_W1cT[HID * KSC];      // W1c^T, [hi | lo]
__device__ __nv_bfloat16 g_xcat[E_MAX * KSC];    // x split [hi | lo]
__device__ float g_ABX  [E_MAX * NBIG];          // [A0 | B0 | x0]
__device__ float g_Ap   [E_MAX * HID];           // A0 + C + b1
__device__ float g_Bp   [E_MAX * HID];           // B0 - C
__device__ float g_xbuf [2][E_MAX * NL];
__device__ float g_sintra[2][E_MAX * NL];
__device__ float g_sinter[2][E_MAX * NL];
__device__ float g_cintra[2][E_MAX];
__device__ float g_cinter[2][E_MAX];
__device__ float g_Wcat [3 * NL * NL];
__device__ float g_losspart[4];
__device__ int   g_done;                         // completion counter (it=2)

// ---------------- warp-mma / cp.async helpers ----------------
__device__ __forceinline__ uint32_t smem_u32(const void* p) {
    uint32_t a;
    asm("{ .reg .u64 t; cvta.to.shared.u64 t, %1; cvt.u32.u64 %0, t; }"
        : "=r"(a) : "l"(p));
    return a;
}
__device__ __forceinline__ void ldmatrix_x4(uint32_t* r, uint32_t addr) {
    asm volatile("ldmatrix.sync.aligned.m8n8.x4.shared.b16 {%0,%1,%2,%3}, [%4];"
                 : "=r"(r[0]), "=r"(r[1]), "=r"(r[2]), "=r"(r[3]) : "r"(addr));
}
__device__ __forceinline__ void ldmatrix_x2(uint32_t* r, uint32_t addr) {
    asm volatile("ldmatrix.sync.aligned.m8n8.x2.shared.b16 {%0,%1}, [%2];"
                 : "=r"(r[0]), "=r"(r[1]) : "r"(addr));
}
__device__ __forceinline__ void mma16816(float* d, const uint32_t* a, const uint32_t* b) {
    asm volatile("mma.sync.aligned.m16n8k16.row.col.f32.bf16.bf16.f32 "
                 "{%0,%1,%2,%3}, {%4,%5,%6,%7}, {%8,%9}, {%0,%1,%2,%3};"
                 : "+f"(d[0]), "+f"(d[1]), "+f"(d[2]), "+f"(d[3])
                 : "r"(a[0]), "r"(a[1]), "r"(a[2]), "r"(a[3]), "r"(b[0]), "r"(b[1]));
}
__device__ __forceinline__ void cp16(uint32_t dst, const void* src, int sz) {
    asm volatile("cp.async.cg.shared.global [%0], [%1], 16, %2;"
                 :: "r"(dst), "l"(src), "r"(sz));
}
__device__ __forceinline__ void cp16u(uint32_t dst, const void* src) {
    asm volatile("cp.async.cg.shared.global [%0], [%1], 16;"
                 :: "r"(dst), "l"(src));
}
#define CP_COMMIT() asm volatile("cp.async.commit_group;" ::: "memory")
#define CP_WAIT1()  asm volatile("cp.async.wait_group 1;" ::: "memory")

#define AROW 80                     // 32 halves (64B) + 16B pad

// ---------------- ONE setup kernel: extract + wtrans + wtransc + prep ---------
#define WTR_B  ((NBIG / 32) * (D_DIM / 32))   // 864
#define WTRC_B ((HID / 32) * (NL / 32))       // 64

__global__ void __launch_bounds__(256) setup_kernel(
    const float* __restrict__ sent,
    const int* __restrict__ esent,
    const int* __restrict__ estart,
    const int* __restrict__ elen,
    const float* __restrict__ W1,
    const float* __restrict__ Wproj,
    const float* __restrict__ Wself,
    const float* __restrict__ Wintra,
    const float* __restrict__ Winter,
    int E)
{
    int b = blockIdx.x;
    int tid = threadIdx.x;

    if (b < E) {                                  // ---- extract ----
        if (tid < D_DIM / 4) {
            int e = b;
            int len = elen[e] + 1;
            int st  = estart[e];
            int snt = esent[e];
            float inv = 1.0f / (float)len;
            const float4* base = (const float4*)(sent + (size_t)snt * S_LEN * D_DIM);
            int d4 = tid;
            float4 acc = make_float4(0.f, 0.f, 0.f, 0.f);
            for (int o = 0; o < len; o++) {
                int idx = st + o; if (idx > S_LEN - 1) idx = S_LEN - 1;
                float4 v = base[(size_t)idx * (D_DIM / 4) + d4];
                acc.x += v.x; acc.y += v.y; acc.z += v.z; acc.w += v.w;
            }
            acc.x *= inv; acc.y *= inv; acc.z *= inv; acc.w *= inv;
            float vv[4] = {acc.x, acc.y, acc.z, acc.w};
            unsigned short h[4], l[4];
            #pragma unroll
            for (int j = 0; j < 4; j++) {
                __nv_bfloat16 hb = __float2bfloat16_rn(vv[j]);
                __nv_bfloat16 lb = __float2bfloat16_rn(vv[j] - __bfloat162float(hb));
                h[j] = __bfloat16_as_ushort(hb);
                l[j] = __bfloat16_as_ushort(lb);
            }
            ushort4* row = (ushort4*)(g_Acat + (size_t)e * KS);
            row[d4]              = make_ushort4(h[0], h[1], h[2], h[3]);
            row[(768 / 4) + d4]  = make_ushort4(l[0], l[1], l[2], l[3]);
        }
        return;
    }
    b -= E;

    if (b < WTR_B) {                              // ---- wtrans (Bcat) ----
        __shared__ float t[32][33];
        int n0 = (b % (NBIG / 32)) * 32, k0 = (b / (NBIG / 32)) * 32;
        int tx = tid & 31, ty = tid >> 5;
        #pragma unroll
        for (int i = 0; i < 32; i += 8) {
            int k = k0 + ty + i, n = n0 + tx;
            float v;
            if (n < 512)        v = W1[(size_t)k * HID + n];
            else if (n < 1024)  v = W1[(size_t)(768 + k) * HID + (n - 512)];
            else                v = Wproj[(size_t)k * NL + (n - 1024)];
            t[ty + i][tx] = v;
        }
        __syncthreads();
        #pragma unroll
        for (int i = 0; i < 32; i += 8) {
            int n = n0 + ty + i, k = k0 + tx;
            float v = t[tx][ty + i];
            __nv_bfloat16 hb = __float2bfloat16_rn(v);
            __nv_bfloat16 lb = __float2bfloat16_rn(v - __bfloat162float(hb));
            g_Bcat[(size_t)n * KS + k]       = hb;
            g_Bcat[(size_t)n * KS + 768 + k] = lb;
        }
        return;
    }
    b -= WTR_B;

    if (b < WTRC_B) {                             // ---- wtransc (W1cT) ----
        __shared__ float t2[32][33];
        const float* W1c = W1 + (size_t)1536 * HID;
        int n0 = (b % (HID / 32)) * 32, k0 = (b / (HID / 32)) * 32;
        int tx = tid & 31, ty = tid >> 5;
        #pragma unroll
        for (int i = 0; i < 32; i += 8) {
            int k = k0 + ty + i, n = n0 + tx;
            t2[ty + i][tx] = W1c[(size_t)k * HID + n];
        }
        __syncthreads();
        #pragma unroll
        for (int i = 0; i < 32; i += 8) {
            int n = n0 + ty + i, k = k0 + tx;
            float v = t2[tx][ty + i];
            __nv_bfloat16 hb = __float2bfloat16_rn(v);
            __nv_bfloat16 lb = __float2bfloat16_rn(v - __bfloat162float(hb));
            g_W1cT[(size_t)n * KSC + k]       = hb;
            g_W1cT[(size_t)n * KSC + 128 + k] = lb;
        }
        return;
    }
    b -= WTRC_B;

    {                                             // ---- prep ----
        long i = (long)b * 256 + tid;
        const long N_WCAT = 3 * NL * NL;
        if (i < N_WCAT) {
            int k = (int)(i / NL), d = (int)(i % NL);
            const float* src = (k < NL) ? Wself : ((k < 2 * NL) ? Wintra : Winter);
            g_Wcat[i] = src[(k % NL) * NL + d];
            return;
        }
        i -= N_WCAT;
        if (i < (long)E * NL) { g_sintra[0][i] = 0.f; g_sinter[0][i] = 0.f; return; }
        i -= (long)E * NL;
        if (i < E) { g_cintra[0][i] = 0.f; g_cinter[0][i] = 0.f; return; }
        i -= E;
        if (i < 4) g_losspart[i] = 0.f;
        if (i == 4) g_done = 0;
    }
}

// ---------------- big mma GEMM: shared-operand bf16x3, 128x128, 3-stage -------
#define BIG_TILE (128 * AROW)               // 10240 per tile
#define BIG_STG  (4 * BIG_TILE)             // 40960 per stage
#define BIG_SMEM (3 * BIG_STG)              // 122880 dynamic

__global__ void __launch_bounds__(256) mma_gemm(
    int E_,
    const __nv_bfloat16* __restrict__ Acat,
    const __nv_bfloat16* __restrict__ Bcat,
    float* __restrict__ Cout,
    __nv_bfloat16* __restrict__ xcat)
{
    extern __shared__ char sm[];
    const int tid  = threadIdx.x;
    const int lane = tid & 31, wid = tid >> 5;
    const int wm = (wid & 1) * 64;
    const int wn = (wid >> 1) * 32;
    const int brow = blockIdx.y * 128;
    const int bcol = blockIdx.x * 128;

    float acc[4][4][4];
    #pragma unroll
    for (int mi = 0; mi < 4; mi++)
        #pragma unroll
        for (int ni = 0; ni < 4; ni++)
            #pragma unroll
            for (int r = 0; r < 4; r++) acc[mi][ni][r] = 0.f;

    auto issue = [&](int c, int s) {
        char* base = sm + s * BIG_STG;
        #pragma unroll
        for (int j = 0; j < 8; j++) {
            int idx  = tid + j * 256;
            int tile = idx >> 9;
            int r    = (idx >> 2) & 127;
            int off  = (idx & 3) * 16;
            uint32_t dst = smem_u32(base + tile * BIG_TILE + r * AROW + off);
            if (tile == 0) {
                int gr = brow + r; int ok = (gr < E_);
                cp16(dst, (const char*)(Acat + (size_t)(ok ? gr : 0) * KS
                                        + (size_t)c * BKH) + off, ok ? 16 : 0);
            } else if (tile == 1) {
                int gr = brow + r; int ok = (gr < E_);
                cp16(dst, (const char*)(Acat + (size_t)(ok ? gr : 0) * KS + 768
                                        + (size_t)c * BKH) + off, ok ? 16 : 0);
            } else if (tile == 2) {
                cp16u(dst, (const char*)(Bcat + (size_t)(bcol + r) * KS
                                         + (size_t)c * BKH) + off);
            } else {
                cp16u(dst, (const char*)(Bcat + (size_t)(bcol + r) * KS + 768
                                         + (size_t)c * BKH) + off);
            }
        }
        CP_COMMIT();
    };

    issue(0, 0);
    issue(1, 1);

    for (int c = 0; c < NCH2; c++) {
        int s = c % 3;
        CP_WAIT1();
        __syncthreads();
        if (c + 2 < NCH2) issue(c + 2, (c + 2) % 3);
        else CP_COMMIT();

        char* base = sm + s * BIG_STG;
        #pragma unroll
        for (int kk = 0; kk < 2; kk++) {
            int aoff = (kk * 16 + (lane >> 4) * 8) * 2;
            int boff = (kk * 16 + ((lane >> 3) & 1) * 8) * 2;
            uint32_t ah[4][4], al[4][4], bh[4][2], bl[4][2];
            #pragma unroll
            for (int mi = 0; mi < 4; mi++) {
                int rr = (wm + mi * 16 + (lane & 15)) * AROW;
                ldmatrix_x4(ah[mi], smem_u32(base + rr + aoff));
                ldmatrix_x4(al[mi], smem_u32(base + BIG_TILE + rr + aoff));
            }
            #pragma unroll
            for (int ni = 0; ni < 4; ni++) {
                int rr = (wn + ni * 8 + (lane & 7)) * AROW;
                ldmatrix_x2(bh[ni], smem_u32(base + 2 * BIG_TILE + rr + boff));
                ldmatrix_x2(bl[ni], smem_u32(base + 3 * BIG_TILE + rr + boff));
            }
            #pragma unroll
            for (int mi = 0; mi < 4; mi++)
                #pragma unroll
                for (int ni = 0; ni < 4; ni++) {
                    mma16816(acc[mi][ni], ah[mi], bh[ni]);
                    mma16816(acc[mi][ni], al[mi], bh[ni]);
                    mma16816(acc[mi][ni], ah[mi], bl[ni]);
                }
        }
    }

    const bool isX = (bcol == 1024);
    #pragma unroll
    for (int mi = 0; mi < 4; mi++) {
        int m0 = brow + wm + mi * 16 + (lane >> 2);
        #pragma unroll
        for (int ni = 0; ni < 4; ni++) {
            int n = bcol + wn + ni * 8 + (lane & 3) * 2;
            #pragma unroll
            for (int half = 0; half < 2; half++) {
                int r = m0 + half * 8;
                if (r >= E_) continue;
                float c0 = acc[mi][ni][half * 2 + 0];
                float c1 = acc[mi][ni][half * 2 + 1];
                *(float2*)(Cout + (size_t)r * NBIG + n) = make_float2(c0, c1);
                if (isX) {
                    int j = n - 1024;
                    __nv_bfloat16 h0 = __float2bfloat16_rn(c0);
                    __nv_bfloat16 l0 = __float2bfloat16_rn(c0 - __bfloat162float(h0));
                    __nv_bfloat16 h1 = __float2bfloat16_rn(c1);
                    __nv_bfloat16 l1 = __float2bfloat16_rn(c1 - __bfloat162float(h1));
                    __nv_bfloat16* xr = xcat + (size_t)r * KSC + j;
                    xr[0] = h0;   xr[1] = h1;
                    xr[128] = l0; xr[129] = l1;
                }
            }
        }
    }
}

// ---------------- cgemm via mma (shared-operand): epi Ap=A0+C+b1, Bp=B0-C -----
#define CG_ATILE (64 * AROW)
#define CG_BTILE (128 * AROW)
#define CG_STG   (2 * CG_ATILE + 2 * CG_BTILE)
#define CG_SMEM  (3 * CG_STG)

__global__ void __launch_bounds__(256) cgemm_mma(
    int E_,
    const __nv_bfloat16* __restrict__ xcat,
    const __nv_bfloat16* __restrict__ W1cT,
    const float* __restrict__ ABX,
    const float* __restrict__ b1,
    float* __restrict__ Ap, float* __restrict__ Bp)
{
    extern __shared__ char sm[];
    const int tid  = threadIdx.x;
    const int lane = tid & 31, wid = tid >> 5;
    const int wm = (wid & 1) * 32;
    const int wn = (wid >> 1) * 32;
    const int brow = blockIdx.y * 64;
    const int bcol = blockIdx.x * 128;

    float acc[2][4][4];
    #pragma unroll
    for (int mi = 0; mi < 2; mi++)
        #pragma unroll
        for (int ni = 0; ni < 4; ni++)
            #pragma unroll
            for (int r = 0; r < 4; r++) acc[mi][ni][r] = 0.f;

    auto issue = [&](int c, int s) {
        char* base = sm + s * CG_STG;
        #pragma unroll
        for (int j = 0; j < 2; j++) {
            int idx  = tid + j * 256;
            int tile = idx >> 8;
            int r    = (idx >> 2) & 63;
            int off  = (idx & 3) * 16;
            int gr = brow + r; int ok = (gr < E_);
            uint32_t dst = smem_u32(base + tile * CG_ATILE + r * AROW + off);
            cp16(dst, (const char*)(xcat + (size_t)(ok ? gr : 0) * KSC
                                    + (tile ? 128 : 0) + (size_t)c * BKH) + off,
                 ok ? 16 : 0);
        }
        #pragma unroll
        for (int j = 0; j < 4; j++) {
            int idx  = tid + j * 256;
            int tile = idx >> 9;
            int r    = (idx >> 2) & 127;
            int off  = (idx & 3) * 16;
            uint32_t dst = smem_u32(base + 2 * CG_ATILE + tile * CG_BTILE + r * AROW + off);
            cp16u(dst, (const char*)(W1cT + (size_t)(bcol + r) * KSC
                                     + (tile ? 128 : 0) + (size_t)c * BKH) + off);
        }
        CP_COMMIT();
    };

    issue(0, 0);
    issue(1, 1);

    for (int c = 0; c < NCHC2; c++) {
        int s = c % 3;
        CP_WAIT1();
        __syncthreads();
        if (c + 2 < NCHC2) issue(c + 2, (c + 2) % 3);
        else CP_COMMIT();

        char* base = sm + s * CG_STG;
        #pragma unroll
        for (int kk = 0; kk < 2; kk++) {
            int aoff = (kk * 16 + (lane >> 4) * 8) * 2;
            int boff = (kk * 16 + ((lane >> 3) & 1) * 8) * 2;
            uint32_t ah[2][4], al[2][4], bh[4][2], bl[4][2];
            #pragma unroll
            for (int mi = 0; mi < 2; mi++) {
                int rr = (wm + mi * 16 + (lane & 15)) * AROW;
                ldmatrix_x4(ah[mi], smem_u32(base + rr + aoff));
                ldmatrix_x4(al[mi], smem_u32(base + CG_ATILE + rr + aoff));
            }
            #pragma unroll
            for (int ni = 0; ni < 4; ni++) {
                int rr = (wn + ni * 8 + (lane & 7)) * AROW;
                ldmatrix_x2(bh[ni], smem_u32(base + 2 * CG_ATILE + rr + boff));
                ldmatrix_x2(bl[ni], smem_u32(base + 2 * CG_ATILE + CG_BTILE + rr + boff));
            }
            #pragma unroll
            for (int mi = 0; mi < 2; mi++)
                #pragma unroll
                for (int ni = 0; ni < 4; ni++) {
                    mma16816(acc[mi][ni], ah[mi], bh[ni]);
                    mma16816(acc[mi][ni], al[mi], bh[ni]);
                    mma16816(acc[mi][ni], ah[mi], bl[ni]);
                }
        }
    }

    #pragma unroll
    for (int mi = 0; mi < 2; mi++) {
        int m0 = brow + wm + mi * 16 + (lane >> 2);
        #pragma unroll
        for (int ni = 0; ni < 4; ni++) {
            int n = bcol + wn + ni * 8 + (lane & 3) * 2;
            float2 b1v = *(const float2*)(b1 + n);
            #pragma unroll
            for (int half = 0; half < 2; half++) {
                int r = m0 + half * 8;
                if (r >= E_) continue;
                float c0 = acc[mi][ni][half * 2 + 0];
                float c1 = acc[mi][ni][half * 2 + 1];
                float2 a0v = *(const float2*)(ABX + (size_t)r * NBIG + n);
                float2 b0v = *(const float2*)(ABX + (size_t)r * NBIG + 512 + n);
                *(float2*)(Ap + (size_t)r * HID + n) =
                    make_float2(a0v.x + c0 + b1v.x, a0v.y + c1 + b1v.y);
                *(float2*)(Bp + (size_t)r * HID + n) =
                    make_float2(b0v.x - c0, b0v.y - c1);
            }
        }
    }
}

// ---------------- fused update GEMM: x_out = relu(Z@Wcat); writes xout + xcat -
__device__ __forceinline__ float4 z_load(
    const float* __restrict__ xin, int xld,
    const float* __restrict__ sintra, const float* __restrict__ sinter,
    const float* __restrict__ cintra, const float* __restrict__ cinter,
    int r, int kg)
{
    int seg = kg >> 7, d = kg & 127;
    if (seg == 0) {
        return *(const float4*)(xin + (size_t)r * xld + d);
    } else if (seg == 1) {
        float4 s = *(const float4*)(sintra + (size_t)r * NL + d);
        float4 xv = *(const float4*)(xin + (size_t)r * xld + d);
        float rc = 0.7f / (cintra[r] + 1.0f);
        return make_float4((s.x + xv.x) * rc, (s.y + xv.y) * rc,
                           (s.z + xv.z) * rc, (s.w + xv.w) * rc);
    } else {
        float4 s = *(const float4*)(sinter + (size_t)r * NL + d);
        float rc = 0.3f / fmaxf(cinter[r], 1.0f);
        return make_float4(s.x * rc, s.y * rc, s.z * rc, s.w * rc);
    }
}

__global__ void __launch_bounds__(256) upd_fused(
    int M,
    const float* __restrict__ xin, int xld,
    const float* __restrict__ sintra, const float* __restrict__ sinter,
    const float* __restrict__ cintra, const float* __restrict__ cinter,
    const float* __restrict__ Wcat,
    float* __restrict__ xout,
    __nv_bfloat16* __restrict__ xcat)
{
    const int BM = 64, BN = 64, BK = 16, KTOT = 3 * NL;
    __shared__ float As[2][BK][BM];
    __shared__ float Bs[2][BK][BN];
    const int tid  = threadIdx.x;
    const int brow = blockIdx.y * BM;
    const int bcol = blockIdx.x * BN;
    const int ar = tid >> 2, ac = (tid & 3) * 4;
    const int br = tid >> 4, bc = (tid & 15) * 4;
    const int tx = tid & 15, ty = tid >> 4;

    float4 areg = make_float4(0.f,0.f,0.f,0.f), breg;
    if (brow + ar < M) areg = z_load(xin, xld, sintra, sinter, cintra, cinter, brow + ar, ac);
    breg = *(const float4*)(Wcat + (size_t)br * NL + bcol + bc);
    As[0][ac+0][ar] = areg.x; As[0][ac+1][ar] = areg.y; As[0][ac+2][ar] = areg.z; As[0][ac+3][ar] = areg.w;
    *(float4*)&Bs[0][br][bc] = breg;
    __syncthreads();

    float acc[4][4];
    #pragma unroll
    for (int i = 0; i < 4; i++)
        #pragma unroll
        for (int j = 0; j < 4; j++) acc[i][j] = 0.f;

    int buf = 0;
    for (int k0 = BK; k0 < KTOT; k0 += BK) {
        areg = make_float4(0.f,0.f,0.f,0.f);
        if (brow + ar < M) areg = z_load(xin, xld, sintra, sinter, cintra, cinter, brow + ar, k0 + ac);
        breg = *(const float4*)(Wcat + (size_t)(k0 + br) * NL + bcol + bc);
        #pragma unroll
        for (int k = 0; k < BK; k++) {
            float av[4], bv[4];
            *(float4*)av = *(const float4*)&As[buf][k][ty * 4];
            *(float4*)bv = *(const float4*)&Bs[buf][k][tx * 4];
            #pragma unroll
            for (int i = 0; i < 4; i++)
                #pragma unroll
                for (int j = 0; j < 4; j++)
                    acc[i][j] = fmaf(av[i], bv[j], acc[i][j]);
        }
        int nb = buf ^ 1;
        As[nb][ac+0][ar] = areg.x; As[nb][ac+1][ar] = areg.y; As[nb][ac+2][ar] = areg.z; As[nb][ac+3][ar] = areg.w;
        *(float4*)&Bs[nb][br][bc] = breg;
        __syncthreads();
        buf = nb;
    }
    #pragma unroll
    for (int k = 0; k < BK; k++) {
        float av[4], bv[4];
        *(float4*)av = *(const float4*)&As[buf][k][ty * 4];
        *(float4*)bv = *(const float4*)&Bs[buf][k][tx * 4];
        #pragma unroll
        for (int i = 0; i < 4; i++)
            #pragma unroll
            for (int j = 0; j < 4; j++)
                acc[i][j] = fmaf(av[i], bv[j], acc[i][j]);
    }

    #pragma unroll
    for (int i = 0; i < 4; i++) {
        int r = brow + ty * 4 + i;
        if (r >= M) continue;
        float o[4];
        o[0] = fmaxf(acc[i][0], 0.f); o[1] = fmaxf(acc[i][1], 0.f);
        o[2] = fmaxf(acc[i][2], 0.f); o[3] = fmaxf(acc[i][3], 0.f);
        int col = bcol + tx * 4;
        *(float4*)(xout + (size_t)r * NL + col) = make_float4(o[0], o[1], o[2], o[3]);
        unsigned short hh[4], ll[4];
        #pragma unroll
        for (int j = 0; j < 4; j++) {
            __nv_bfloat16 hb = __float2bfloat16_rn(o[j]);
            __nv_bfloat16 lb = __float2bfloat16_rn(o[j] - __bfloat162float(hb));
            hh[j] = __bfloat16_as_ushort(hb);
            ll[j] = __bfloat16_as_ushort(lb);
        }
        __nv_bfloat16* xr = xcat + (size_t)r * KSC;
        *(ushort4*)(xr + col)       = make_ushort4(hh[0], hh[1], hh[2], hh[3]);
        *(ushort4*)(xr + 128 + col) = make_ushort4(ll[0], ll[1], ll[2], ll[3]);
    }
}

// ---------------- per-pair: 256 thr, 32 pairs/block (4 per warp) --------------
__global__ void __launch_bounds__(256) pair_kernel(
    const float* __restrict__ Ap, const float* __restrict__ Bp,
    const float* __restrict__ xin, int xld,
    const float* __restrict__ W2, const float* __restrict__ b2,
    const int* __restrict__ pair1, const int* __restrict__ pair2,
    const int* __restrict__ rtype, const int* __restrict__ targ,
    float* sintra, float* sinter, float* cintra, float* cinter,
    float* si_o, float* se_o, float* ci_o, float* ce_o,
    float* lossacc, float* logits_out,
    const float* lp_base, float* loss_out, int isLast,
    int P, int E)
{
    __shared__ float W2s0[HID], W2s1[HID], W2s2[HID];
    __shared__ float b2s[CLS];
    __shared__ float ce_s[8];
    int tid = threadIdx.x;
    for (int i = tid; i < HID; i += 256) {
        W2s0[i] = W2[i * 3 + 0];
        W2s1[i] = W2[i * 3 + 1];
        W2s2[i] = W2[i * 3 + 2];
    }
    if (tid < CLS) b2s[tid] = b2[tid];

    {
        long idx = (long)blockIdx.x * 256 + tid;
        long stride = (long)gridDim.x * 256;
        for (long i = idx; i < (long)E * NL; i += stride) { si_o[i] = 0.f; se_o[i] = 0.f; }
        for (long i = idx; i < E; i += stride) { ci_o[i] = 0.f; ce_o[i] = 0.f; }
    }
    __syncthreads();

    int warp = tid >> 5, lane = tid & 31;
    float ce_sum = 0.f;
    #pragma unroll
    for (int sub = 0; sub < 4; sub++) {
        int p = blockIdx.x * 32 + warp * 4 + sub;
        if (p >= P) continue;
        int p1 = pair1[p], p2 = pair2[p];
        const float4* a4 = (const float4*)(Ap + (size_t)p1 * HID);
        const float4* b4 = (const float4*)(Bp + (size_t)p2 * HID);
        float a0 = 0.f, a1 = 0.f, a2 = 0.f;
        #pragma unroll
        for (int j = 0; j < 4; j++) {
            int i4 = j * 32 + lane;
            float4 av = a4[i4], bv = b4[i4];
            float4 h;
            h.x = fmaxf(av.x + bv.x, 0.f);
            h.y = fmaxf(av.y + bv.y, 0.f);
            h.z = fmaxf(av.z + bv.z, 0.f);
            h.w = fmaxf(av.w + bv.w, 0.f);
            int base = i4 * 4;
            float4 w0 = *(const float4*)&W2s0[base];
            float4 w1 = *(const float4*)&W2s1[base];
            float4 w2 = *(const float4*)&W2s2[base];
            a0 = fmaf(h.x, w0.x, fmaf(h.y, w0.y, fmaf(h.z, w0.z, fmaf(h.w, w0.w, a0))));
            a1 = fmaf(h.x, w1.x, fmaf(h.y, w1.y, fmaf(h.z, w1.z, fmaf(h.w, w1.w, a1))));
            a2 = fmaf(h.x, w2.x, fmaf(h.y, w2.y, fmaf(h.z, w2.z, fmaf(h.w, w2.w, a2))));
        }
        #pragma unroll
        for (int o = 16; o; o >>= 1) {
            a0 += __shfl_xor_sync(0xffffffffu, a0, o);
            a1 += __shfl_xor_sync(0xffffffffu, a1, o);
            a2 += __shfl_xor_sync(0xffffffffu, a2, o);
        }
        float l0 = a0 + b2s[0], l1 = a1 + b2s[1], l2 = a2 + b2s[2];
        float m = fmaxf(l0, fmaxf(l1, l2));
        float s = expf(l0 - m) + expf(l1 - m) + expf(l2 - m);
        int tg = targ[p];
        float lt = (tg == 0) ? l0 : ((tg == 1) ? l1 : l2);
        ce_sum += logf(s) + m - lt;
        if (logits_out != nullptr && lane == 0) {
            logits_out[(size_t)p * 3 + 0] = l0;
            logits_out[(size_t)p * 3 + 1] = l1;
            logits_out[(size_t)p * 3 + 2] = l2;
        }
        int argm = 0; float mm = l0;
        if (l1 > mm) { mm = l1; argm = 1; }
        if (l2 > mm) { mm = l2; argm = 2; }
        bool conf = (1.0f / s) > 0.3f;
        int rt = rtype[p];
        if (conf && (argm == 1 || argm == 2)) {
            bool srcIs1 = (argm == 1);
            int src = srcIs1 ? p1 : p2;
            int dst = srcIs1 ? p2 : p1;
            float* sb = (rt == 0) ? sintra : sinter;
            float* cb = (rt == 0) ? cintra : cinter;
            const float* xs = xin + (size_t)src * xld;
            #pragma unroll
            for (int j = 0; j < NL / 32; j++) {
                int d = j * 32 + lane;
                atomicAdd(&sb[(size_t)dst * NL + d], xs[d]);
            }
            if (lane == 0) atomicAdd(&cb[dst], 1.0f);
        }
    }
    if (lane == 0) ce_s[warp] = ce_sum;
    __syncthreads();
    if (tid == 0) {
        float t = ce_s[0] + ce_s[1] + ce_s[2] + ce_s[3]
                + ce_s[4] + ce_s[5] + ce_s[6] + ce_s[7];
        atomicAdd(lossacc, t);
        if (isLast) {
            __threadfence();
            int v = atomicAdd(&g_done, 1);
            if (v == (int)gridDim.x - 1) {
                volatile const float* lv = lp_base;
                loss_out[0] = (lv[0] + lv[1] * 0.5f + lv[2] * (1.0f / 3.0f)) / (float)P;
            }
        }
    }
}

// ---------------- launch ------------------------------------------------------
extern "C" void kernel_launch(void* const* d_in, const int* in_sizes, int n_in,
                              void* d_out, int out_size)
{
    const float* sent   = (const float*)d_in[0];
    const float* Wproj  = (const float*)d_in[1];
    const float* W1     = (const float*)d_in[2];
    const float* b1     = (const float*)d_in[3];
    const float* W2     = (const float*)d_in[4];
    const float* b2     = (const float*)d_in[5];
    const float* Wself  = (const float*)d_in[6];
    const float* Wintra = (const float*)d_in[7];
    const float* Winter = (const float*)d_in[8];
    const int* esent  = (const int*)d_in[9];
    const int* estart = (const int*)d_in[10];
    const int* elen   = (const int*)d_in[11];
    const int* pair1  = (const int*)d_in[12];
    const int* pair2  = (const int*)d_in[13];
    const int* rtype  = (const int*)d_in[14];
    const int* targ   = (const int*)d_in[15];
    float* out = (float*)d_out;

    int E = in_sizes[9];
    int P = in_sizes[12];
    if (E > E_MAX) E = E_MAX;
    if (P > P_MAX) P = P_MAX;

    __nv_bfloat16 *Acat, *Bcat, *W1cT, *xcat;
    float *ABX, *Ap, *Bp, *lp, *Wcat;
    float *xb[2], *si[2], *se[2], *ci[2], *ce[2];
    cudaGetSymbolAddress((void**)&Acat, g_Acat);
    cudaGetSymbolAddress((void**)&Bcat, g_Bcat);
    cudaGetSymbolAddress((void**)&W1cT, g_W1cT);
    cudaGetSymbolAddress((void**)&xcat, g_xcat);
    cudaGetSymbolAddress((void**)&ABX,  g_ABX);
    cudaGetSymbolAddress((void**)&Ap,   g_Ap);
    cudaGetSymbolAddress((void**)&Bp,   g_Bp);
    cudaGetSymbolAddress((void**)&Wcat, g_Wcat);
    cudaGetSymbolAddress((void**)&lp,   g_losspart);
    {
        float* base;
        cudaGetSymbolAddress((void**)&base, g_xbuf);
        xb[0] = base; xb[1] = base + E_MAX * NL;
        cudaGetSymbolAddress((void**)&base, g_sintra);
        si[0] = base; si[1] = base + E_MAX * NL;
        cudaGetSymbolAddress((void**)&base, g_sinter);
        se[0] = base; se[1] = base + E_MAX * NL;
        cudaGetSymbolAddress((void**)&base, g_cintra);
        ci[0] = base; ci[1] = base + E_MAX;
        cudaGetSymbolAddress((void**)&base, g_cinter);
        ce[0] = base; ce[1] = base + E_MAX;
    }

    int loff = out_size - 3 * P;
    if (loff < 0) loff = 0;
    float* logits_out = out + loff;

    // 1) one setup launch (also resets g_done)
    {
        int prepb = (int)((3L * NL * NL + (long)E * NL + E + 4 + 1 + 255) / 256);
        int total = E + WTR_B + WTRC_B + prepb;
        setup_kernel<<<total, 256>>>(sent, esent, estart, elen,
                                     W1, Wproj, Wself, Wintra, Winter, E);
    }

    // 2) tensor-core big GEMM (also emits xcat for it=0)
    cudaFuncSetAttribute(mma_gemm, cudaFuncAttributeMaxDynamicSharedMemorySize, BIG_SMEM);
    cudaFuncSetAttribute(cgemm_mma, cudaFuncAttributeMaxDynamicSharedMemorySize, CG_SMEM);
    {
        dim3 g(NBIG / 128, (E_MAX + 127) / 128);   // 9 x 16 = 144 CTAs
        mma_gemm<<<g, 256, BIG_SMEM>>>(E, Acat, Bcat, ABX, xcat);
    }

    // 3) three iterations
    for (int it = 0; it < 3; it++) {
        int ph = it & 1, po = ph ^ 1;
        const float* xin = (it == 0) ? (ABX + 1024) : xb[(it - 1) & 1];
        int xld = (it == 0) ? NBIG : NL;
        float* xout = xb[it & 1];

        {
            dim3 g(HID / 128, (E + 63) / 64);     // 4 x 32
            cgemm_mma<<<g, 256, CG_SMEM>>>(E, xcat, W1cT, ABX, b1, Ap, Bp);
        }
        pair_kernel<<<(P + 31) / 32, 256>>>(Ap, Bp, xin, xld, W2, b2,
                                          pair1, pair2, rtype, targ,
                                          si[ph], se[ph], ci[ph], ce[ph],
                                          si[po], se[po], ci[po], ce[po],
                                          lp + it, (it == 2) ? logits_out : nullptr,
                                          lp, out, (it == 2) ? 1 : 0, P, E);
        if (it < 2) {
            dim3 g(NL / 64, (E + 63) / 64);
            upd_fused<<<g, 256>>>(E, xin, xld,
                                  si[ph], se[ph], ci[ph], ce[ph],
                                  Wcat, xout, xcat);
        }
    }
}

// round 16
// speedup vs baseline: 1.2327x; 1.0138x over previous
#include <cuda_runtime.h>
#include <cuda_bf16.h>
#include <math.h>
#include <stdint.h>

#define NSENT 64
#define S_LEN 512
#define D_DIM 768
#define NL    128
#define HID   512
#define CLS   3
#define E_MAX 2000
#define P_MAX 20000
#define NBIG  1152            // 512(A0) + 512(B0) + 128(x0)
#define KS    1536            // 2*768: [hi | lo]
#define KSC   256             // 2*128: [hi | lo]
#define BKH   32              // K-halves per chunk
#define NCH2  (D_DIM / BKH)   // 24
#define NCHH  (NCH2 / 2)      // 12 chunks per K-half
#define NCHC2 (NL / BKH)      // 4

// ---------------- static device scratch ----------------
__device__ __nv_bfloat16 g_Acat[E_MAX * KS];     // [hi | lo]
__device__ __nv_bfloat16 g_Bcat[NBIG * KS];      // W^T, [hi | lo]
__device__ __nv_bfloat16 g_W1cT[HID * KSC];      // W1c^T, [hi | lo]
__device__ __nv_bfloat16 g_xcat[E_MAX * KSC];    // x split [hi | lo]
__device__ float g_part [2][E_MAX * NBIG];       // split-K partials
__device__ float g_ABX  [E_MAX * NBIG];          // [A0 | B0 | x0]
__device__ float g_Ap   [E_MAX * HID];           // A0 + C + b1
__device__ float g_Bp   [E_MAX * HID];           // B0 - C
__device__ float g_xbuf [2][E_MAX * NL];
__device__ float g_sintra[2][E_MAX * NL];
__device__ float g_sinter[2][E_MAX * NL];
__device__ float g_cintra[2][E_MAX];
__device__ float g_cinter[2][E_MAX];
__device__ float g_Wcat [3 * NL * NL];
__device__ float g_losspart[4];
__device__ int   g_done;                         // completion counter (it=2)

// ---------------- warp-mma / cp.async helpers ----------------
__device__ __forceinline__ uint32_t smem_u32(const void* p) {
    uint32_t a;
    asm("{ .reg .u64 t; cvta.to.shared.u64 t, %1; cvt.u32.u64 %0, t; }"
        : "=r"(a) : "l"(p));
    return a;
}
__device__ __forceinline__ void ldmatrix_x4(uint32_t* r, uint32_t addr) {
    asm volatile("ldmatrix.sync.aligned.m8n8.x4.shared.b16 {%0,%1,%2,%3}, [%4];"
                 : "=r"(r[0]), "=r"(r[1]), "=r"(r[2]), "=r"(r[3]) : "r"(addr));
}
__device__ __forceinline__ void ldmatrix_x2(uint32_t* r, uint32_t addr) {
    asm volatile("ldmatrix.sync.aligned.m8n8.x2.shared.b16 {%0,%1}, [%2];"
                 : "=r"(r[0]), "=r"(r[1]) : "r"(addr));
}
__device__ __forceinline__ void mma16816(float* d, const uint32_t* a, const uint32_t* b) {
    asm volatile("mma.sync.aligned.m16n8k16.row.col.f32.bf16.bf16.f32 "
                 "{%0,%1,%2,%3}, {%4,%5,%6,%7}, {%8,%9}, {%0,%1,%2,%3};"
                 : "+f"(d[0]), "+f"(d[1]), "+f"(d[2]), "+f"(d[3])
                 : "r"(a[0]), "r"(a[1]), "r"(a[2]), "r"(a[3]), "r"(b[0]), "r"(b[1]));
}
__device__ __forceinline__ void cp16(uint32_t dst, const void* src, int sz) {
    asm volatile("cp.async.cg.shared.global [%0], [%1], 16, %2;"
                 :: "r"(dst), "l"(src), "r"(sz));
}
__device__ __forceinline__ void cp16u(uint32_t dst, const void* src) {
    asm volatile("cp.async.cg.shared.global [%0], [%1], 16;"
                 :: "r"(dst), "l"(src));
}
#define CP_COMMIT() asm volatile("cp.async.commit_group;" ::: "memory")
#define CP_WAIT1()  asm volatile("cp.async.wait_group 1;" ::: "memory")

#define AROW 80                     // 32 halves (64B) + 16B pad

// ---------------- ONE setup kernel: extract + wtrans + wtransc + prep ---------
#define WTR_B  ((NBIG / 32) * (D_DIM / 32))   // 864
#define WTRC_B ((HID / 32) * (NL / 32))       // 64

__global__ void __launch_bounds__(256) setup_kernel(
    const float* __restrict__ sent,
    const int* __restrict__ esent,
    const int* __restrict__ estart,
    const int* __restrict__ elen,
    const float* __restrict__ W1,
    const float* __restrict__ Wproj,
    const float* __restrict__ Wself,
    const float* __restrict__ Wintra,
    const float* __restrict__ Winter,
    int E)
{
    int b = blockIdx.x;
    int tid = threadIdx.x;

    if (b < E) {                                  // ---- extract ----
        if (tid < D_DIM / 4) {
            int e = b;
            int len = elen[e] + 1;
            int st  = estart[e];
            int snt = esent[e];
            float inv = 1.0f / (float)len;
            const float4* base = (const float4*)(sent + (size_t)snt * S_LEN * D_DIM);
            int d4 = tid;
            float4 acc = make_float4(0.f, 0.f, 0.f, 0.f);
            for (int o = 0; o < len; o++) {
                int idx = st + o; if (idx > S_LEN - 1) idx = S_LEN - 1;
                float4 v = base[(size_t)idx * (D_DIM / 4) + d4];
                acc.x += v.x; acc.y += v.y; acc.z += v.z; acc.w += v.w;
            }
            acc.x *= inv; acc.y *= inv; acc.z *= inv; acc.w *= inv;
            float vv[4] = {acc.x, acc.y, acc.z, acc.w};
            unsigned short h[4], l[4];
            #pragma unroll
            for (int j = 0; j < 4; j++) {
                __nv_bfloat16 hb = __float2bfloat16_rn(vv[j]);
                __nv_bfloat16 lb = __float2bfloat16_rn(vv[j] - __bfloat162float(hb));
                h[j] = __bfloat16_as_ushort(hb);
                l[j] = __bfloat16_as_ushort(lb);
            }
            ushort4* row = (ushort4*)(g_Acat + (size_t)e * KS);
            row[d4]              = make_ushort4(h[0], h[1], h[2], h[3]);
            row[(768 / 4) + d4]  = make_ushort4(l[0], l[1], l[2], l[3]);
        }
        return;
    }
    b -= E;

    if (b < WTR_B) {                              // ---- wtrans (Bcat) ----
        __shared__ float t[32][33];
        int n0 = (b % (NBIG / 32)) * 32, k0 = (b / (NBIG / 32)) * 32;
        int tx = tid & 31, ty = tid >> 5;
        #pragma unroll
        for (int i = 0; i < 32; i += 8) {
            int k = k0 + ty + i, n = n0 + tx;
            float v;
            if (n < 512)        v = W1[(size_t)k * HID + n];
            else if (n < 1024)  v = W1[(size_t)(768 + k) * HID + (n - 512)];
            else                v = Wproj[(size_t)k * NL + (n - 1024)];
            t[ty + i][tx] = v;
        }
        __syncthreads();
        #pragma unroll
        for (int i = 0; i < 32; i += 8) {
            int n = n0 + ty + i, k = k0 + tx;
            float v = t[tx][ty + i];
            __nv_bfloat16 hb = __float2bfloat16_rn(v);
            __nv_bfloat16 lb = __float2bfloat16_rn(v - __bfloat162float(hb));
            g_Bcat[(size_t)n * KS + k]       = hb;
            g_Bcat[(size_t)n * KS + 768 + k] = lb;
        }
        return;
    }
    b -= WTR_B;

    if (b < WTRC_B) {                             // ---- wtransc (W1cT) ----
        __shared__ float t2[32][33];
        const float* W1c = W1 + (size_t)1536 * HID;
        int n0 = (b % (HID / 32)) * 32, k0 = (b / (HID / 32)) * 32;
        int tx = tid & 31, ty = tid >> 5;
        #pragma unroll
        for (int i = 0; i < 32; i += 8) {
            int k = k0 + ty + i, n = n0 + tx;
            t2[ty + i][tx] = W1c[(size_t)k * HID + n];
        }
        __syncthreads();
        #pragma unroll
        for (int i = 0; i < 32; i += 8) {
            int n = n0 + ty + i, k = k0 + tx;
            float v = t2[tx][ty + i];
            __nv_bfloat16 hb = __float2bfloat16_rn(v);
            __nv_bfloat16 lb = __float2bfloat16_rn(v - __bfloat162float(hb));
            g_W1cT[(size_t)n * KSC + k]       = hb;
            g_W1cT[(size_t)n * KSC + 128 + k] = lb;
        }
        return;
    }
    b -= WTRC_B;

    {                                             // ---- prep ----
        long i = (long)b * 256 + tid;
        const long N_WCAT = 3 * NL * NL;
        if (i < N_WCAT) {
            int k = (int)(i / NL), d = (int)(i % NL);
            const float* src = (k < NL) ? Wself : ((k < 2 * NL) ? Wintra : Winter);
            g_Wcat[i] = src[(k % NL) * NL + d];
            return;
        }
        i -= N_WCAT;
        if (i < (long)E * NL) { g_sintra[0][i] = 0.f; g_sinter[0][i] = 0.f; return; }
        i -= (long)E * NL;
        if (i < E) { g_cintra[0][i] = 0.f; g_cinter[0][i] = 0.f; return; }
        i -= E;
        if (i < 4) g_losspart[i] = 0.f;
        if (i == 4) g_done = 0;
    }
}

// ---------------- big mma GEMM split-K: 128x128 tiles, 2-stage, grid z=2 ------
#define BIG_TILE (128 * AROW)               // 10240 per tile
#define BIG_STG  (4 * BIG_TILE)             // 40960 per stage
#define SK_SMEM  (2 * BIG_STG)              // 81920 dynamic (2-stage)

__global__ void __launch_bounds__(256, 2) mma_gemm_sk(
    int E_,
    const __nv_bfloat16* __restrict__ Acat,
    const __nv_bfloat16* __restrict__ Bcat,
    float* __restrict__ Pout)               // partial for this K-half
{
    extern __shared__ char sm[];
    const int tid  = threadIdx.x;
    const int lane = tid & 31, wid = tid >> 5;
    const int wm = (wid & 1) * 64;
    const int wn = (wid >> 1) * 32;
    const int brow = blockIdx.y * 128;
    const int bcol = blockIdx.x * 128;
    const int cbase = blockIdx.z * NCHH;
    float* myP = Pout + (size_t)blockIdx.z * E_MAX * NBIG;

    float acc[4][4][4];
    #pragma unroll
    for (int mi = 0; mi < 4; mi++)
        #pragma unroll
        for (int ni = 0; ni < 4; ni++)
            #pragma unroll
            for (int r = 0; r < 4; r++) acc[mi][ni][r] = 0.f;

    auto issue = [&](int c, int s) {
        char* base = sm + s * BIG_STG;
        #pragma unroll
        for (int j = 0; j < 8; j++) {
            int idx  = tid + j * 256;
            int tile = idx >> 9;
            int r    = (idx >> 2) & 127;
            int off  = (idx & 3) * 16;
            uint32_t dst = smem_u32(base + tile * BIG_TILE + r * AROW + off);
            if (tile == 0) {
                int gr = brow + r; int ok = (gr < E_);
                cp16(dst, (const char*)(Acat + (size_t)(ok ? gr : 0) * KS
                                        + (size_t)c * BKH) + off, ok ? 16 : 0);
            } else if (tile == 1) {
                int gr = brow + r; int ok = (gr < E_);
                cp16(dst, (const char*)(Acat + (size_t)(ok ? gr : 0) * KS + 768
                                        + (size_t)c * BKH) + off, ok ? 16 : 0);
            } else if (tile == 2) {
                cp16u(dst, (const char*)(Bcat + (size_t)(bcol + r) * KS
                                         + (size_t)c * BKH) + off);
            } else {
                cp16u(dst, (const char*)(Bcat + (size_t)(bcol + r) * KS + 768
                                         + (size_t)c * BKH) + off);
            }
        }
        CP_COMMIT();
    };

    issue(cbase, 0);

    for (int c = 0; c < NCHH; c++) {
        int s = c & 1;
        if (c + 1 < NCHH) issue(cbase + c + 1, s ^ 1);
        else CP_COMMIT();
        CP_WAIT1();
        __syncthreads();

        char* base = sm + s * BIG_STG;
        #pragma unroll
        for (int kk = 0; kk < 2; kk++) {
            int aoff = (kk * 16 + (lane >> 4) * 8) * 2;
            int boff = (kk * 16 + ((lane >> 3) & 1) * 8) * 2;
            uint32_t ah[4][4], bh[4][2];
            #pragma unroll
            for (int mi = 0; mi < 4; mi++)
                ldmatrix_x4(ah[mi], smem_u32(base + (wm + mi * 16 + (lane & 15)) * AROW + aoff));
            #pragma unroll
            for (int ni = 0; ni < 4; ni++)
                ldmatrix_x2(bh[ni], smem_u32(base + 2 * BIG_TILE + (wn + ni * 8 + (lane & 7)) * AROW + boff));
            #pragma unroll
            for (int mi = 0; mi < 4; mi++)
                #pragma unroll
                for (int ni = 0; ni < 4; ni++)
                    mma16816(acc[mi][ni], ah[mi], bh[ni]);
            // pass 2: al * bh (al reuses liveness after pass1)
            {
                uint32_t al[4][4];
                #pragma unroll
                for (int mi = 0; mi < 4; mi++)
                    ldmatrix_x4(al[mi], smem_u32(base + BIG_TILE + (wm + mi * 16 + (lane & 15)) * AROW + aoff));
                #pragma unroll
                for (int mi = 0; mi < 4; mi++)
                    #pragma unroll
                    for (int ni = 0; ni < 4; ni++)
                        mma16816(acc[mi][ni], al[mi], bh[ni]);
            }
            // pass 3: ah * bl
            {
                uint32_t bl[4][2];
                #pragma unroll
                for (int ni = 0; ni < 4; ni++)
                    ldmatrix_x2(bl[ni], smem_u32(base + 3 * BIG_TILE + (wn + ni * 8 + (lane & 7)) * AROW + boff));
                #pragma unroll
                for (int mi = 0; mi < 4; mi++)
                    #pragma unroll
                    for (int ni = 0; ni < 4; ni++)
                        mma16816(acc[mi][ni], ah[mi], bl[ni]);
            }
        }
        __syncthreads();
    }

    #pragma unroll
    for (int mi = 0; mi < 4; mi++) {
        int m0 = brow + wm + mi * 16 + (lane >> 2);
        #pragma unroll
        for (int ni = 0; ni < 4; ni++) {
            int n = bcol + wn + ni * 8 + (lane & 3) * 2;
            #pragma unroll
            for (int half = 0; half < 2; half++) {
                int r = m0 + half * 8;
                if (r >= E_) continue;
                *(float2*)(myP + (size_t)r * NBIG + n) =
                    make_float2(acc[mi][ni][half * 2 + 0], acc[mi][ni][half * 2 + 1]);
            }
        }
    }
}

// ---------------- fixup: ABX = P0 + P1; emit xcat from x-columns --------------
__global__ void __launch_bounds__(256) fixup_kernel(
    int E_,
    const float* __restrict__ p0, const float* __restrict__ p1,
    float* __restrict__ ABX, __nv_bfloat16* __restrict__ xcat)
{
    long n4 = (long)E_ * NBIG / 4;
    long stride = (long)gridDim.x * 256;
    for (long i = (long)blockIdx.x * 256 + threadIdx.x; i < n4; i += stride) {
        float4 a = ((const float4*)p0)[i];
        float4 b = ((const float4*)p1)[i];
        float4 s = make_float4(a.x + b.x, a.y + b.y, a.z + b.z, a.w + b.w);
        ((float4*)ABX)[i] = s;
        long flat = i * 4;
        int col = (int)(flat % NBIG);
        if (col >= 1024) {
            int row = (int)(flat / NBIG);
            int j = col - 1024;
            float vv[4] = {s.x, s.y, s.z, s.w};
            unsigned short hh[4], ll[4];
            #pragma unroll
            for (int q = 0; q < 4; q++) {
                __nv_bfloat16 hb = __float2bfloat16_rn(vv[q]);
                __nv_bfloat16 lb = __float2bfloat16_rn(vv[q] - __bfloat162float(hb));
                hh[q] = __bfloat16_as_ushort(hb);
                ll[q] = __bfloat16_as_ushort(lb);
            }
            __nv_bfloat16* xr = xcat + (size_t)row * KSC;
            *(ushort4*)(xr + j)       = make_ushort4(hh[0], hh[1], hh[2], hh[3]);
            *(ushort4*)(xr + 128 + j) = make_ushort4(ll[0], ll[1], ll[2], ll[3]);
        }
    }
}

// ---------------- cgemm via mma (shared-operand): epi Ap=A0+C+b1, Bp=B0-C -----
#define CG_ATILE (64 * AROW)
#define CG_BTILE (128 * AROW)
#define CG_STG   (2 * CG_ATILE + 2 * CG_BTILE)
#define CG_SMEM  (3 * CG_STG)

__global__ void __launch_bounds__(256) cgemm_mma(
    int E_,
    const __nv_bfloat16* __restrict__ xcat,
    const __nv_bfloat16* __restrict__ W1cT,
    const float* __restrict__ ABX,
    const float* __restrict__ b1,
    float* __restrict__ Ap, float* __restrict__ Bp)
{
    extern __shared__ char sm[];
    const int tid  = threadIdx.x;
    const int lane = tid & 31, wid = tid >> 5;
    const int wm = (wid & 1) * 32;
    const int wn = (wid >> 1) * 32;
    const int brow = blockIdx.y * 64;
    const int bcol = blockIdx.x * 128;

    float acc[2][4][4];
    #pragma unroll
    for (int mi = 0; mi < 2; mi++)
        #pragma unroll
        for (int ni = 0; ni < 4; ni++)
            #pragma unroll
            for (int r = 0; r < 4; r++) acc[mi][ni][r] = 0.f;

    auto issue = [&](int c, int s) {
        char* base = sm + s * CG_STG;
        #pragma unroll
        for (int j = 0; j < 2; j++) {
            int idx  = tid + j * 256;
            int tile = idx >> 8;
            int r    = (idx >> 2) & 63;
            int off  = (idx & 3) * 16;
            int gr = brow + r; int ok = (gr < E_);
            uint32_t dst = smem_u32(base + tile * CG_ATILE + r * AROW + off);
            cp16(dst, (const char*)(xcat + (size_t)(ok ? gr : 0) * KSC
                                    + (tile ? 128 : 0) + (size_t)c * BKH) + off,
                 ok ? 16 : 0);
        }
        #pragma unroll
        for (int j = 0; j < 4; j++) {
            int idx  = tid + j * 256;
            int tile = idx >> 9;
            int r    = (idx >> 2) & 127;
            int off  = (idx & 3) * 16;
            uint32_t dst = smem_u32(base + 2 * CG_ATILE + tile * CG_BTILE + r * AROW + off);
            cp16u(dst, (const char*)(W1cT + (size_t)(bcol + r) * KSC
                                     + (tile ? 128 : 0) + (size_t)c * BKH) + off);
        }
        CP_COMMIT();
    };

    issue(0, 0);
    issue(1, 1);

    for (int c = 0; c < NCHC2; c++) {
        int s = c % 3;
        CP_WAIT1();
        __syncthreads();
        if (c + 2 < NCHC2) issue(c + 2, (c + 2) % 3);
        else CP_COMMIT();

        char* base = sm + s * CG_STG;
        #pragma unroll
        for (int kk = 0; kk < 2; kk++) {
            int aoff = (kk * 16 + (lane >> 4) * 8) * 2;
            int boff = (kk * 16 + ((lane >> 3) & 1) * 8) * 2;
            uint32_t ah[2][4], bh[4][2];
            #pragma unroll
            for (int mi = 0; mi < 2; mi++)
                ldmatrix_x4(ah[mi], smem_u32(base + (wm + mi * 16 + (lane & 15)) * AROW + aoff));
            #pragma unroll
            for (int ni = 0; ni < 4; ni++)
                ldmatrix_x2(bh[ni], smem_u32(base + 2 * CG_ATILE + (wn + ni * 8 + (lane & 7)) * AROW + boff));
            #pragma unroll
            for (int mi = 0; mi < 2; mi++)
                #pragma unroll
                for (int ni = 0; ni < 4; ni++)
                    mma16816(acc[mi][ni], ah[mi], bh[ni]);
            {
                uint32_t al[2][4];
                #pragma unroll
                for (int mi = 0; mi < 2; mi++)
                    ldmatrix_x4(al[mi], smem_u32(base + CG_ATILE + (wm + mi * 16 + (lane & 15)) * AROW + aoff));
                #pragma unroll
                for (int mi = 0; mi < 2; mi++)
                    #pragma unroll
                    for (int ni = 0; ni < 4; ni++)
                        mma16816(acc[mi][ni], al[mi], bh[ni]);
            }
            {
                uint32_t bl[4][2];
                #pragma unroll
                for (int ni = 0; ni < 4; ni++)
                    ldmatrix_x2(bl[ni], smem_u32(base + 2 * CG_ATILE + CG_BTILE + (wn + ni * 8 + (lane & 7)) * AROW + boff));
                #pragma unroll
                for (int mi = 0; mi < 2; mi++)
                    #pragma unroll
                    for (int ni = 0; ni < 4; ni++)
                        mma16816(acc[mi][ni], ah[mi], bl[ni]);
            }
        }
    }

    #pragma unroll
    for (int mi = 0; mi < 2; mi++) {
        int m0 = brow + wm + mi * 16 + (lane >> 2);
        #pragma unroll
        for (int ni = 0; ni < 4; ni++) {
            int n = bcol + wn + ni * 8 + (lane & 3) * 2;
            float2 b1v = *(const float2*)(b1 + n);
            #pragma unroll
            for (int half = 0; half < 2; half++) {
                int r = m0 + half * 8;
                if (r >= E_) continue;
                float c0 = acc[mi][ni][half * 2 + 0];
                float c1 = acc[mi][ni][half * 2 + 1];
                float2 a0v = *(const float2*)(ABX + (size_t)r * NBIG + n);
                float2 b0v = *(const float2*)(ABX + (size_t)r * NBIG + 512 + n);
                *(float2*)(Ap + (size_t)r * HID + n) =
                    make_float2(a0v.x + c0 + b1v.x, a0v.y + c1 + b1v.y);
                *(float2*)(Bp + (size_t)r * HID + n) =
                    make_float2(b0v.x - c0, b0v.y - c1);
            }
        }
    }
}

// ---------------- fused update GEMM: x_out = relu(Z@Wcat); writes xout + xcat -
__device__ __forceinline__ float4 z_load(
    const float* __restrict__ xin, int xld,
    const float* __restrict__ sintra, const float* __restrict__ sinter,
    const float* __restrict__ cintra, const float* __restrict__ cinter,
    int r, int kg)
{
    int seg = kg >> 7, d = kg & 127;
    if (seg == 0) {
        return *(const float4*)(xin + (size_t)r * xld + d);
    } else if (seg == 1) {
        float4 s = *(const float4*)(sintra + (size_t)r * NL + d);
        float4 xv = *(const float4*)(xin + (size_t)r * xld + d);
        float rc = 0.7f / (cintra[r] + 1.0f);
        return make_float4((s.x + xv.x) * rc, (s.y + xv.y) * rc,
                           (s.z + xv.z) * rc, (s.w + xv.w) * rc);
    } else {
        float4 s = *(const float4*)(sinter + (size_t)r * NL + d);
        float rc = 0.3f / fmaxf(cinter[r], 1.0f);
        return make_float4(s.x * rc, s.y * rc, s.z * rc, s.w * rc);
    }
}

__global__ void __launch_bounds__(256) upd_fused(
    int M,
    const float* __restrict__ xin, int xld,
    const float* __restrict__ sintra, const float* __restrict__ sinter,
    const float* __restrict__ cintra, const float* __restrict__ cinter,
    const float* __restrict__ Wcat,
    float* __restrict__ xout,
    __nv_bfloat16* __restrict__ xcat)
{
    const int BM = 64, BN = 64, BK = 16, KTOT = 3 * NL;
    __shared__ float As[2][BK][BM];
    __shared__ float Bs[2][BK][BN];
    const int tid  = threadIdx.x;
    const int brow = blockIdx.y * BM;
    const int bcol = blockIdx.x * BN;
    const int ar = tid >> 2, ac = (tid & 3) * 4;
    const int br = tid >> 4, bc = (tid & 15) * 4;
    const int tx = tid & 15, ty = tid >> 4;

    float4 areg = make_float4(0.f,0.f,0.f,0.f), breg;
    if (brow + ar < M) areg = z_load(xin, xld, sintra, sinter, cintra, cinter, brow + ar, ac);
    breg = *(const float4*)(Wcat + (size_t)br * NL + bcol + bc);
    As[0][ac+0][ar] = areg.x; As[0][ac+1][ar] = areg.y; As[0][ac+2][ar] = areg.z; As[0][ac+3][ar] = areg.w;
    *(float4*)&Bs[0][br][bc] = breg;
    __syncthreads();

    float acc[4][4];
    #pragma unroll
    for (int i = 0; i < 4; i++)
        #pragma unroll
        for (int j = 0; j < 4; j++) acc[i][j] = 0.f;

    int buf = 0;
    for (int k0 = BK; k0 < KTOT; k0 += BK) {
        areg = make_float4(0.f,0.f,0.f,0.f);
        if (brow + ar < M) areg = z_load(xin, xld, sintra, sinter, cintra, cinter, brow + ar, k0 + ac);
        breg = *(const float4*)(Wcat + (size_t)(k0 + br) * NL + bcol + bc);
        #pragma unroll
        for (int k = 0; k < BK; k++) {
            float av[4], bv[4];
            *(float4*)av = *(const float4*)&As[buf][k][ty * 4];
            *(float4*)bv = *(const float4*)&Bs[buf][k][tx * 4];
            #pragma unroll
            for (int i = 0; i < 4; i++)
                #pragma unroll
                for (int j = 0; j < 4; j++)
                    acc[i][j] = fmaf(av[i], bv[j], acc[i][j]);
        }
        int nb = buf ^ 1;
        As[nb][ac+0][ar] = areg.x; As[nb][ac+1][ar] = areg.y; As[nb][ac+2][ar] = areg.z; As[nb][ac+3][ar] = areg.w;
        *(float4*)&Bs[nb][br][bc] = breg;
        __syncthreads();
        buf = nb;
    }
    #pragma unroll
    for (int k = 0; k < BK; k++) {
        float av[4], bv[4];
        *(float4*)av = *(const float4*)&As[buf][k][ty * 4];
        *(float4*)bv = *(const float4*)&Bs[buf][k][tx * 4];
        #pragma unroll
        for (int i = 0; i < 4; i++)
            #pragma unroll
            for (int j = 0; j < 4; j++)
                acc[i][j] = fmaf(av[i], bv[j], acc[i][j]);
    }

    #pragma unroll
    for (int i = 0; i < 4; i++) {
        int r = brow + ty * 4 + i;
        if (r >= M) continue;
        float o[4];
        o[0] = fmaxf(acc[i][0], 0.f); o[1] = fmaxf(acc[i][1], 0.f);
        o[2] = fmaxf(acc[i][2], 0.f); o[3] = fmaxf(acc[i][3], 0.f);
        int col = bcol + tx * 4;
        *(float4*)(xout + (size_t)r * NL + col) = make_float4(o[0], o[1], o[2], o[3]);
        unsigned short hh[4], ll[4];
        #pragma unroll
        for (int j = 0; j < 4; j++) {
            __nv_bfloat16 hb = __float2bfloat16_rn(o[j]);
            __nv_bfloat16 lb = __float2bfloat16_rn(o[j] - __bfloat162float(hb));
            hh[j] = __bfloat16_as_ushort(hb);
            ll[j] = __bfloat16_as_ushort(lb);
        }
        __nv_bfloat16* xr = xcat + (size_t)r * KSC;
        *(ushort4*)(xr + col)       = make_ushort4(hh[0], hh[1], hh[2], hh[3]);
        *(ushort4*)(xr + 128 + col) = make_ushort4(ll[0], ll[1], ll[2], ll[3]);
    }
}

// ---------------- per-pair: 256 thr, 32 pairs/block (4 per warp) --------------
__global__ void __launch_bounds__(256) pair_kernel(
    const float* __restrict__ Ap, const float* __restrict__ Bp,
    const float* __restrict__ xin, int xld,
    const float* __restrict__ W2, const float* __restrict__ b2,
    const int* __restrict__ pair1, const int* __restrict__ pair2,
    const int* __restrict__ rtype, const int* __restrict__ targ,
    float* sintra, float* sinter, float* cintra, float* cinter,
    float* si_o, float* se_o, float* ci_o, float* ce_o,
    float* lossacc, float* logits_out,
    const float* lp_base, float* loss_out, int isLast,
    int P, int E)
{
    __shared__ float W2s0[HID], W2s1[HID], W2s2[HID];
    __shared__ float b2s[CLS];
    __shared__ float ce_s[8];
    int tid = threadIdx.x;
    for (int i = tid; i < HID; i += 256) {
        W2s0[i] = W2[i * 3 + 0];
        W2s1[i] = W2[i * 3 + 1];
        W2s2[i] = W2[i * 3 + 2];
    }
    if (tid < CLS) b2s[tid] = b2[tid];

    {
        long idx = (long)blockIdx.x * 256 + tid;
        long stride = (long)gridDim.x * 256;
        for (long i = idx; i < (long)E * NL; i += stride) { si_o[i] = 0.f; se_o[i] = 0.f; }
        for (long i = idx; i < E; i += stride) { ci_o[i] = 0.f; ce_o[i] = 0.f; }
    }
    __syncthreads();

    int warp = tid >> 5, lane = tid & 31;
    float ce_sum = 0.f;
    #pragma unroll
    for (int sub = 0; sub < 4; sub++) {
        int p = blockIdx.x * 32 + warp * 4 + sub;
        if (p >= P) continue;
        int p1 = pair1[p], p2 = pair2[p];
        const float4* a4 = (const float4*)(Ap + (size_t)p1 * HID);
        const float4* b4 = (const float4*)(Bp + (size_t)p2 * HID);
        float a0 = 0.f, a1 = 0.f, a2 = 0.f;
        #pragma unroll
        for (int j = 0; j < 4; j++) {
            int i4 = j * 32 + lane;
            float4 av = a4[i4], bv = b4[i4];
            float4 h;
            h.x = fmaxf(av.x + bv.x, 0.f);
            h.y = fmaxf(av.y + bv.y, 0.f);
            h.z = fmaxf(av.z + bv.z, 0.f);
            h.w = fmaxf(av.w + bv.w, 0.f);
            int base = i4 * 4;
            float4 w0 = *(const float4*)&W2s0[base];
            float4 w1 = *(const float4*)&W2s1[base];
            float4 w2 = *(const float4*)&W2s2[base];
            a0 = fmaf(h.x, w0.x, fmaf(h.y, w0.y, fmaf(h.z, w0.z, fmaf(h.w, w0.w, a0))));
            a1 = fmaf(h.x, w1.x, fmaf(h.y, w1.y, fmaf(h.z, w1.z, fmaf(h.w, w1.w, a1))));
            a2 = fmaf(h.x, w2.x, fmaf(h.y, w2.y, fmaf(h.z, w2.z, fmaf(h.w, w2.w, a2))));
        }
        #pragma unroll
        for (int o = 16; o; o >>= 1) {
            a0 += __shfl_xor_sync(0xffffffffu, a0, o);
            a1 += __shfl_xor_sync(0xffffffffu, a1, o);
            a2 += __shfl_xor_sync(0xffffffffu, a2, o);
        }
        float l0 = a0 + b2s[0], l1 = a1 + b2s[1], l2 = a2 + b2s[2];
        float m = fmaxf(l0, fmaxf(l1, l2));
        float s = expf(l0 - m) + expf(l1 - m) + expf(l2 - m);
        int tg = targ[p];
        float lt = (tg == 0) ? l0 : ((tg == 1) ? l1 : l2);
        ce_sum += logf(s) + m - lt;
        if (logits_out != nullptr && lane == 0) {
            logits_out[(size_t)p * 3 + 0] = l0;
            logits_out[(size_t)p * 3 + 1] = l1;
            logits_out[(size_t)p * 3 + 2] = l2;
        }
        int argm = 0; float mm = l0;
        if (l1 > mm) { mm = l1; argm = 1; }
        if (l2 > mm) { mm = l2; argm = 2; }
        bool conf = (1.0f / s) > 0.3f;
        int rt = rtype[p];
        if (conf && (argm == 1 || argm == 2)) {
            bool srcIs1 = (argm == 1);
            int src = srcIs1 ? p1 : p2;
            int dst = srcIs1 ? p2 : p1;
            float* sb = (rt == 0) ? sintra : sinter;
            float* cb = (rt == 0) ? cintra : cinter;
            const float* xs = xin + (size_t)src * xld;
            #pragma unroll
            for (int j = 0; j < NL / 32; j++) {
                int d = j * 32 + lane;
                atomicAdd(&sb[(size_t)dst * NL + d], xs[d]);
            }
            if (lane == 0) atomicAdd(&cb[dst], 1.0f);
        }
    }
    if (lane == 0) ce_s[warp] = ce_sum;
    __syncthreads();
    if (tid == 0) {
        float t = ce_s[0] + ce_s[1] + ce_s[2] + ce_s[3]
                + ce_s[4] + ce_s[5] + ce_s[6] + ce_s[7];
        atomicAdd(lossacc, t);
        if (isLast) {
            __threadfence();
            int v = atomicAdd(&g_done, 1);
            if (v == (int)gridDim.x - 1) {
                volatile const float* lv = lp_base;
                loss_out[0] = (lv[0] + lv[1] * 0.5f + lv[2] * (1.0f / 3.0f)) / (float)P;
            }
        }
    }
}

// ---------------- launch ------------------------------------------------------
extern "C" void kernel_launch(void* const* d_in, const int* in_sizes, int n_in,
                              void* d_out, int out_size)
{
    const float* sent   = (const float*)d_in[0];
    const float* Wproj  = (const float*)d_in[1];
    const float* W1     = (const float*)d_in[2];
    const float* b1     = (const float*)d_in[3];
    const float* W2     = (const float*)d_in[4];
    const float* b2     = (const float*)d_in[5];
    const float* Wself  = (const float*)d_in[6];
    const float* Wintra = (const float*)d_in[7];
    const float* Winter = (const float*)d_in[8];
    const int* esent  = (const int*)d_in[9];
    const int* estart = (const int*)d_in[10];
    const int* elen   = (const int*)d_in[11];
    const int* pair1  = (const int*)d_in[12];
    const int* pair2  = (const int*)d_in[13];
    const int* rtype  = (const int*)d_in[14];
    const int* targ   = (const int*)d_in[15];
    float* out = (float*)d_out;

    int E = in_sizes[9];
    int P = in_sizes[12];
    if (E > E_MAX) E = E_MAX;
    if (P > P_MAX) P = P_MAX;

    __nv_bfloat16 *Acat, *Bcat, *W1cT, *xcat;
    float *ABX, *Ap, *Bp, *lp, *Wcat, *part;
    float *xb[2], *si[2], *se[2], *ci[2], *ce[2];
    cudaGetSymbolAddress((void**)&Acat, g_Acat);
    cudaGetSymbolAddress((void**)&Bcat, g_Bcat);
    cudaGetSymbolAddress((void**)&W1cT, g_W1cT);
    cudaGetSymbolAddress((void**)&xcat, g_xcat);
    cudaGetSymbolAddress((void**)&ABX,  g_ABX);
    cudaGetSymbolAddress((void**)&Ap,   g_Ap);
    cudaGetSymbolAddress((void**)&Bp,   g_Bp);
    cudaGetSymbolAddress((void**)&Wcat, g_Wcat);
    cudaGetSymbolAddress((void**)&lp,   g_losspart);
    cudaGetSymbolAddress((void**)&part, g_part);
    {
        float* base;
        cudaGetSymbolAddress((void**)&base, g_xbuf);
        xb[0] = base; xb[1] = base + E_MAX * NL;
        cudaGetSymbolAddress((void**)&base, g_sintra);
        si[0] = base; si[1] = base + E_MAX * NL;
        cudaGetSymbolAddress((void**)&base, g_sinter);
        se[0] = base; se[1] = base + E_MAX * NL;
        cudaGetSymbolAddress((void**)&base, g_cintra);
        ci[0] = base; ci[1] = base + E_MAX;
        cudaGetSymbolAddress((void**)&base, g_cinter);
        ce[0] = base; ce[1] = base + E_MAX;
    }

    int loff = out_size - 3 * P;
    if (loff < 0) loff = 0;
    float* logits_out = out + loff;

    // 1) one setup launch (also resets g_done)
    {
        int prepb = (int)((3L * NL * NL + (long)E * NL + E + 4 + 1 + 255) / 256);
        int total = E + WTR_B + WTRC_B + prepb;
        setup_kernel<<<total, 256>>>(sent, esent, estart, elen,
                                     W1, Wproj, Wself, Wintra, Winter, E);
    }

    // 2) split-K tensor-core big GEMM + fixup (sums partials, emits xcat)
    cudaFuncSetAttribute(mma_gemm_sk, cudaFuncAttributeMaxDynamicSharedMemorySize, SK_SMEM);
    cudaFuncSetAttribute(cgemm_mma, cudaFuncAttributeMaxDynamicSharedMemorySize, CG_SMEM);
    {
        dim3 g(NBIG / 128, (E_MAX + 127) / 128, 2);   // 9 x 16 x 2 = 288 CTAs
        mma_gemm_sk<<<g, 256, SK_SMEM>>>(E, Acat, Bcat, part);
        fixup_kernel<<<1184, 256>>>(E, part, part + (size_t)E_MAX * NBIG, ABX, xcat);
    }

    // 3) three iterations
    for (int it = 0; it < 3; it++) {
        int ph = it & 1, po = ph ^ 1;
        const float* xin = (it == 0) ? (ABX + 1024) : xb[(it - 1) & 1];
        int xld = (it == 0) ? NBIG : NL;
        float* xout = xb[it & 1];

        {
            dim3 g(HID / 128, (E + 63) / 64);     // 4 x 32
            cgemm_mma<<<g, 256, CG_SMEM>>>(E, xcat, W1cT, ABX, b1, Ap, Bp);
        }
        pair_kernel<<<(P + 31) / 32, 256>>>(Ap, Bp, xin, xld, W2, b2,
                                          pair1, pair2, rtype, targ,
                                          si[ph], se[ph], ci[ph], ce[ph],
                                          si[po], se[po], ci[po], ce[po],
                                          lp + it, (it == 2) ? logits_out : nullptr,
                                          lp, out, (it == 2) ? 1 : 0, P, E);
        if (it < 2) {
            dim3 g(NL / 64, (E + 63) / 64);
            upd_fused<<<g, 256>>>(E, xin, xld,
                                  si[ph], se[ph], ci[ph], ce[ph],
                                  Wcat, xout, xcat);
        }
    }
}

// round 17
// speedup vs baseline: 1.2514x; 1.0152x over previous
#include <cuda_runtime.h>
#include <cuda_bf16.h>
#include <math.h>
#include <stdint.h>

#define NSENT 64
#define S_LEN 512
#define D_DIM 768
#define NL    128
#define HID   512
#define CLS   3
#define E_MAX 2000
#define P_MAX 20000
#define NBIG  1152            // 512(A0) + 512(B0) + 128(x0)
#define KS    1536            // 2*768: [hi | lo]
#define KSC   256             // 2*128: [hi | lo]
#define BKH   32              // K-halves per chunk
#define NCH2  (D_DIM / BKH)   // 24
#define NCHH  (NCH2 / 2)      // 12 chunks per K-half
#define NCHC2 (NL / BKH)      // 4

// ---------------- static device scratch ----------------
__device__ __nv_bfloat16 g_Acat[E_MAX * KS];     // [hi | lo]
__device__ __nv_bfloat16 g_Bcat[NBIG * KS];      // W^T, [hi | lo]
__device__ __nv_bfloat16 g_W1cT[HID * KSC];      // W1c^T, [hi | lo]
__device__ __nv_bfloat16 g_xcat[E_MAX * KSC];    // x split [hi | lo]
__device__ float g_part [2][E_MAX * NBIG];       // split-K partials
__device__ float g_ABX  [E_MAX * NBIG];          // [A0 | B0 | x0]
__device__ float g_Ap   [E_MAX * HID];           // A0 + C + b1
__device__ float g_Bp   [E_MAX * HID];           // B0 - C
__device__ float g_xbuf [2][E_MAX * NL];
__device__ float g_sintra[2][E_MAX * NL];
__device__ float g_sinter[2][E_MAX * NL];
__device__ float g_cintra[2][E_MAX];
__device__ float g_cinter[2][E_MAX];
__device__ float g_Wcat [3 * NL * NL];
__device__ float g_losspart[4];
__device__ int   g_done;                         // completion counter (it=2)

// ---------------- warp-mma / cp.async helpers ----------------
__device__ __forceinline__ uint32_t smem_u32(const void* p) {
    uint32_t a;
    asm("{ .reg .u64 t; cvta.to.shared.u64 t, %1; cvt.u32.u64 %0, t; }"
        : "=r"(a) : "l"(p));
    return a;
}
__device__ __forceinline__ void ldmatrix_x4(uint32_t* r, uint32_t addr) {
    asm volatile("ldmatrix.sync.aligned.m8n8.x4.shared.b16 {%0,%1,%2,%3}, [%4];"
                 : "=r"(r[0]), "=r"(r[1]), "=r"(r[2]), "=r"(r[3]) : "r"(addr));
}
__device__ __forceinline__ void ldmatrix_x2(uint32_t* r, uint32_t addr) {
    asm volatile("ldmatrix.sync.aligned.m8n8.x2.shared.b16 {%0,%1}, [%2];"
                 : "=r"(r[0]), "=r"(r[1]) : "r"(addr));
}
__device__ __forceinline__ void mma16816(float* d, const uint32_t* a, const uint32_t* b) {
    asm volatile("mma.sync.aligned.m16n8k16.row.col.f32.bf16.bf16.f32 "
                 "{%0,%1,%2,%3}, {%4,%5,%6,%7}, {%8,%9}, {%0,%1,%2,%3};"
                 : "+f"(d[0]), "+f"(d[1]), "+f"(d[2]), "+f"(d[3])
                 : "r"(a[0]), "r"(a[1]), "r"(a[2]), "r"(a[3]), "r"(b[0]), "r"(b[1]));
}
__device__ __forceinline__ void cp16(uint32_t dst, const void* src, int sz) {
    asm volatile("cp.async.cg.shared.global [%0], [%1], 16, %2;"
                 :: "r"(dst), "l"(src), "r"(sz));
}
__device__ __forceinline__ void cp16u(uint32_t dst, const void* src) {
    asm volatile("cp.async.cg.shared.global [%0], [%1], 16;"
                 :: "r"(dst), "l"(src));
}
#define CP_COMMIT() asm volatile("cp.async.commit_group;" ::: "memory")
#define CP_WAIT1()  asm volatile("cp.async.wait_group 1;" ::: "memory")

#define AROW 80                     // 32 halves (64B) + 16B pad

// ---------------- ONE setup kernel: extract + wtrans + wtransc + prep ---------
#define WTR_B  ((NBIG / 32) * (D_DIM / 32))   // 864
#define WTRC_B ((HID / 32) * (NL / 32))       // 64

__global__ void __launch_bounds__(256) setup_kernel(
    const float* __restrict__ sent,
    const int* __restrict__ esent,
    const int* __restrict__ estart,
    const int* __restrict__ elen,
    const float* __restrict__ W1,
    const float* __restrict__ Wproj,
    const float* __restrict__ Wself,
    const float* __restrict__ Wintra,
    const float* __restrict__ Winter,
    int E)
{
    int b = blockIdx.x;
    int tid = threadIdx.x;

    if (b < E) {                                  // ---- extract ----
        if (tid < D_DIM / 4) {
            int e = b;
            int len = elen[e] + 1;
            int st  = estart[e];
            int snt = esent[e];
            float inv = 1.0f / (float)len;
            const float4* base = (const float4*)(sent + (size_t)snt * S_LEN * D_DIM);
            int d4 = tid;
            float4 acc = make_float4(0.f, 0.f, 0.f, 0.f);
            for (int o = 0; o < len; o++) {
                int idx = st + o; if (idx > S_LEN - 1) idx = S_LEN - 1;
                float4 v = base[(size_t)idx * (D_DIM / 4) + d4];
                acc.x += v.x; acc.y += v.y; acc.z += v.z; acc.w += v.w;
            }
            acc.x *= inv; acc.y *= inv; acc.z *= inv; acc.w *= inv;
            float vv[4] = {acc.x, acc.y, acc.z, acc.w};
            unsigned short h[4], l[4];
            #pragma unroll
            for (int j = 0; j < 4; j++) {
                __nv_bfloat16 hb = __float2bfloat16_rn(vv[j]);
                __nv_bfloat16 lb = __float2bfloat16_rn(vv[j] - __bfloat162float(hb));
                h[j] = __bfloat16_as_ushort(hb);
                l[j] = __bfloat16_as_ushort(lb);
            }
            ushort4* row = (ushort4*)(g_Acat + (size_t)e * KS);
            row[d4]              = make_ushort4(h[0], h[1], h[2], h[3]);
            row[(768 / 4) + d4]  = make_ushort4(l[0], l[1], l[2], l[3]);
        }
        return;
    }
    b -= E;

    if (b < WTR_B) {                              // ---- wtrans (Bcat) ----
        __shared__ float t[32][33];
        int n0 = (b % (NBIG / 32)) * 32, k0 = (b / (NBIG / 32)) * 32;
        int tx = tid & 31, ty = tid >> 5;
        #pragma unroll
        for (int i = 0; i < 32; i += 8) {
            int k = k0 + ty + i, n = n0 + tx;
            float v;
            if (n < 512)        v = W1[(size_t)k * HID + n];
            else if (n < 1024)  v = W1[(size_t)(768 + k) * HID + (n - 512)];
            else                v = Wproj[(size_t)k * NL + (n - 1024)];
            t[ty + i][tx] = v;
        }
        __syncthreads();
        #pragma unroll
        for (int i = 0; i < 32; i += 8) {
            int n = n0 + ty + i, k = k0 + tx;
            float v = t[tx][ty + i];
            __nv_bfloat16 hb = __float2bfloat16_rn(v);
            __nv_bfloat16 lb = __float2bfloat16_rn(v - __bfloat162float(hb));
            g_Bcat[(size_t)n * KS + k]       = hb;
            g_Bcat[(size_t)n * KS + 768 + k] = lb;
        }
        return;
    }
    b -= WTR_B;

    if (b < WTRC_B) {                             // ---- wtransc (W1cT) ----
        __shared__ float t2[32][33];
        const float* W1c = W1 + (size_t)1536 * HID;
        int n0 = (b % (HID / 32)) * 32, k0 = (b / (HID / 32)) * 32;
        int tx = tid & 31, ty = tid >> 5;
        #pragma unroll
        for (int i = 0; i < 32; i += 8) {
            int k = k0 + ty + i, n = n0 + tx;
            t2[ty + i][tx] = W1c[(size_t)k * HID + n];
        }
        __syncthreads();
        #pragma unroll
        for (int i = 0; i < 32; i += 8) {
            int n = n0 + ty + i, k = k0 + tx;
            float v = t2[tx][ty + i];
            __nv_bfloat16 hb = __float2bfloat16_rn(v);
            __nv_bfloat16 lb = __float2bfloat16_rn(v - __bfloat162float(hb));
            g_W1cT[(size_t)n * KSC + k]       = hb;
            g_W1cT[(size_t)n * KSC + 128 + k] = lb;
        }
        return;
    }
    b -= WTRC_B;

    {                                             // ---- prep ----
        long i = (long)b * 256 + tid;
        const long N_WCAT = 3 * NL * NL;
        if (i < N_WCAT) {
            int k = (int)(i / NL), d = (int)(i % NL);
            const float* src = (k < NL) ? Wself : ((k < 2 * NL) ? Wintra : Winter);
            g_Wcat[i] = src[(k % NL) * NL + d];
            return;
        }
        i -= N_WCAT;
        if (i < (long)E * NL) { g_sintra[0][i] = 0.f; g_sinter[0][i] = 0.f; return; }
        i -= (long)E * NL;
        if (i < E) { g_cintra[0][i] = 0.f; g_cinter[0][i] = 0.f; return; }
        i -= E;
        if (i < 4) g_losspart[i] = 0.f;
        if (i == 4) g_done = 0;
    }
}

// ---------------- big mma GEMM split-K: 128x128 tiles, 2-stage, grid z=2 ------
#define BIG_TILE (128 * AROW)               // 10240 per tile
#define BIG_STG  (4 * BIG_TILE)             // 40960 per stage
#define SK_SMEM  (2 * BIG_STG)              // 81920 dynamic (2-stage)

__global__ void __launch_bounds__(256, 2) mma_gemm_sk(
    int E_,
    const __nv_bfloat16* __restrict__ Acat,
    const __nv_bfloat16* __restrict__ Bcat,
    float* __restrict__ Pout)               // partial for this K-half
{
    extern __shared__ char sm[];
    const int tid  = threadIdx.x;
    const int lane = tid & 31, wid = tid >> 5;
    const int wm = (wid & 1) * 64;
    const int wn = (wid >> 1) * 32;
    const int brow = blockIdx.y * 128;
    const int bcol = blockIdx.x * 128;
    const int cbase = blockIdx.z * NCHH;
    float* myP = Pout + (size_t)blockIdx.z * E_MAX * NBIG;

    float acc[4][4][4];
    #pragma unroll
    for (int mi = 0; mi < 4; mi++)
        #pragma unroll
        for (int ni = 0; ni < 4; ni++)
            #pragma unroll
            for (int r = 0; r < 4; r++) acc[mi][ni][r] = 0.f;

    auto issue = [&](int c, int s) {
        char* base = sm + s * BIG_STG;
        #pragma unroll
        for (int j = 0; j < 8; j++) {
            int idx  = tid + j * 256;
            int tile = idx >> 9;
            int r    = (idx >> 2) & 127;
            int off  = (idx & 3) * 16;
            uint32_t dst = smem_u32(base + tile * BIG_TILE + r * AROW + off);
            if (tile == 0) {
                int gr = brow + r; int ok = (gr < E_);
                cp16(dst, (const char*)(Acat + (size_t)(ok ? gr : 0) * KS
                                        + (size_t)c * BKH) + off, ok ? 16 : 0);
            } else if (tile == 1) {
                int gr = brow + r; int ok = (gr < E_);
                cp16(dst, (const char*)(Acat + (size_t)(ok ? gr : 0) * KS + 768
                                        + (size_t)c * BKH) + off, ok ? 16 : 0);
            } else if (tile == 2) {
                cp16u(dst, (const char*)(Bcat + (size_t)(bcol + r) * KS
                                         + (size_t)c * BKH) + off);
            } else {
                cp16u(dst, (const char*)(Bcat + (size_t)(bcol + r) * KS + 768
                                         + (size_t)c * BKH) + off);
            }
        }
        CP_COMMIT();
    };

    issue(cbase, 0);

    for (int c = 0; c < NCHH; c++) {
        int s = c & 1;
        if (c + 1 < NCHH) issue(cbase + c + 1, s ^ 1);
        else CP_COMMIT();
        CP_WAIT1();
        __syncthreads();

        char* base = sm + s * BIG_STG;
        #pragma unroll
        for (int kk = 0; kk < 2; kk++) {
            int aoff = (kk * 16 + (lane >> 4) * 8) * 2;
            int boff = (kk * 16 + ((lane >> 3) & 1) * 8) * 2;
            uint32_t ah[4][4], bh[4][2];
            #pragma unroll
            for (int mi = 0; mi < 4; mi++)
                ldmatrix_x4(ah[mi], smem_u32(base + (wm + mi * 16 + (lane & 15)) * AROW + aoff));
            #pragma unroll
            for (int ni = 0; ni < 4; ni++)
                ldmatrix_x2(bh[ni], smem_u32(base + 2 * BIG_TILE + (wn + ni * 8 + (lane & 7)) * AROW + boff));
            #pragma unroll
            for (int mi = 0; mi < 4; mi++)
                #pragma unroll
                for (int ni = 0; ni < 4; ni++)
                    mma16816(acc[mi][ni], ah[mi], bh[ni]);
            {
                uint32_t al[4][4];
                #pragma unroll
                for (int mi = 0; mi < 4; mi++)
                    ldmatrix_x4(al[mi], smem_u32(base + BIG_TILE + (wm + mi * 16 + (lane & 15)) * AROW + aoff));
                #pragma unroll
                for (int mi = 0; mi < 4; mi++)
                    #pragma unroll
                    for (int ni = 0; ni < 4; ni++)
                        mma16816(acc[mi][ni], al[mi], bh[ni]);
            }
            {
                uint32_t bl[4][2];
                #pragma unroll
                for (int ni = 0; ni < 4; ni++)
                    ldmatrix_x2(bl[ni], smem_u32(base + 3 * BIG_TILE + (wn + ni * 8 + (lane & 7)) * AROW + boff));
                #pragma unroll
                for (int mi = 0; mi < 4; mi++)
                    #pragma unroll
                    for (int ni = 0; ni < 4; ni++)
                        mma16816(acc[mi][ni], ah[mi], bl[ni]);
            }
        }
        __syncthreads();
    }

    #pragma unroll
    for (int mi = 0; mi < 4; mi++) {
        int m0 = brow + wm + mi * 16 + (lane >> 2);
        #pragma unroll
        for (int ni = 0; ni < 4; ni++) {
            int n = bcol + wn + ni * 8 + (lane & 3) * 2;
            #pragma unroll
            for (int half = 0; half < 2; half++) {
                int r = m0 + half * 8;
                if (r >= E_) continue;
                *(float2*)(myP + (size_t)r * NBIG + n) =
                    make_float2(acc[mi][ni][half * 2 + 0], acc[mi][ni][half * 2 + 1]);
            }
        }
    }
}

// ---------------- fixup: ABX = P0 + P1; emit xcat from x-columns --------------
__global__ void __launch_bounds__(256) fixup_kernel(
    int E_,
    const float* __restrict__ p0, const float* __restrict__ p1,
    float* __restrict__ ABX, __nv_bfloat16* __restrict__ xcat)
{
    long n4 = (long)E_ * NBIG / 4;
    long stride = (long)gridDim.x * 256;
    for (long i = (long)blockIdx.x * 256 + threadIdx.x; i < n4; i += stride) {
        float4 a = ((const float4*)p0)[i];
        float4 b = ((const float4*)p1)[i];
        float4 s = make_float4(a.x + b.x, a.y + b.y, a.z + b.z, a.w + b.w);
        ((float4*)ABX)[i] = s;
        long flat = i * 4;
        int col = (int)(flat % NBIG);
        if (col >= 1024) {
            int row = (int)(flat / NBIG);
            int j = col - 1024;
            float vv[4] = {s.x, s.y, s.z, s.w};
            unsigned short hh[4], ll[4];
            #pragma unroll
            for (int q = 0; q < 4; q++) {
                __nv_bfloat16 hb = __float2bfloat16_rn(vv[q]);
                __nv_bfloat16 lb = __float2bfloat16_rn(vv[q] - __bfloat162float(hb));
                hh[q] = __bfloat16_as_ushort(hb);
                ll[q] = __bfloat16_as_ushort(lb);
            }
            __nv_bfloat16* xr = xcat + (size_t)row * KSC;
            *(ushort4*)(xr + j)       = make_ushort4(hh[0], hh[1], hh[2], hh[3]);
            *(ushort4*)(xr + 128 + j) = make_ushort4(ll[0], ll[1], ll[2], ll[3]);
        }
    }
}

// ---------------- cgemm via mma: 64x64 tiles, 2 CTAs/SM -----------------------
#define CG_T64   (64 * AROW)                // 5120
#define CG_STG   (4 * CG_T64)               // 20480 per stage (Ahi,Alo,Bhi,Blo)
#define CG_SMEM  (3 * CG_STG)               // 61440 dynamic

__global__ void __launch_bounds__(256, 2) cgemm_mma(
    int E_,
    const __nv_bfloat16* __restrict__ xcat,
    const __nv_bfloat16* __restrict__ W1cT,
    const float* __restrict__ ABX,
    const float* __restrict__ b1,
    float* __restrict__ Ap, float* __restrict__ Bp)
{
    extern __shared__ char sm[];
    const int tid  = threadIdx.x;
    const int lane = tid & 31, wid = tid >> 5;
    const int wm = (wid & 1) * 32;          // 2 warp-rows of 32
    const int wn = (wid >> 1) * 16;         // 4 warp-cols of 16
    const int brow = blockIdx.y * 64;
    const int bcol = blockIdx.x * 64;

    float acc[2][2][4];
    #pragma unroll
    for (int mi = 0; mi < 2; mi++)
        #pragma unroll
        for (int ni = 0; ni < 2; ni++)
            #pragma unroll
            for (int r = 0; r < 4; r++) acc[mi][ni][r] = 0.f;

    auto issue = [&](int c, int s) {
        char* base = sm + s * CG_STG;
        // A: 2 tiles x 64 rows x 4 chunks = 512 cp
        #pragma unroll
        for (int j = 0; j < 2; j++) {
            int idx  = tid + j * 256;
            int tile = idx >> 8;             // 0: hi, 1: lo
            int r    = (idx >> 2) & 63;
            int off  = (idx & 3) * 16;
            int gr = brow + r; int ok = (gr < E_);
            uint32_t dst = smem_u32(base + tile * CG_T64 + r * AROW + off);
            cp16(dst, (const char*)(xcat + (size_t)(ok ? gr : 0) * KSC
                                    + (tile ? 128 : 0) + (size_t)c * BKH) + off,
                 ok ? 16 : 0);
        }
        // B: 2 tiles x 64 rows x 4 chunks = 512 cp
        #pragma unroll
        for (int j = 0; j < 2; j++) {
            int idx  = tid + j * 256;
            int tile = idx >> 8;             // 0: hi, 1: lo
            int r    = (idx >> 2) & 63;
            int off  = (idx & 3) * 16;
            uint32_t dst = smem_u32(base + (2 + tile) * CG_T64 + r * AROW + off);
            cp16u(dst, (const char*)(W1cT + (size_t)(bcol + r) * KSC
                                     + (tile ? 128 : 0) + (size_t)c * BKH) + off);
        }
        CP_COMMIT();
    };

    issue(0, 0);
    issue(1, 1);

    for (int c = 0; c < NCHC2; c++) {
        int s = c % 3;
        CP_WAIT1();
        __syncthreads();
        if (c + 2 < NCHC2) issue(c + 2, (c + 2) % 3);
        else CP_COMMIT();

        char* base = sm + s * CG_STG;
        #pragma unroll
        for (int kk = 0; kk < 2; kk++) {
            int aoff = (kk * 16 + (lane >> 4) * 8) * 2;
            int boff = (kk * 16 + ((lane >> 3) & 1) * 8) * 2;
            uint32_t ah[2][4], bh[2][2];
            #pragma unroll
            for (int mi = 0; mi < 2; mi++)
                ldmatrix_x4(ah[mi], smem_u32(base + (wm + mi * 16 + (lane & 15)) * AROW + aoff));
            #pragma unroll
            for (int ni = 0; ni < 2; ni++)
                ldmatrix_x2(bh[ni], smem_u32(base + 2 * CG_T64 + (wn + ni * 8 + (lane & 7)) * AROW + boff));
            #pragma unroll
            for (int mi = 0; mi < 2; mi++)
                #pragma unroll
                for (int ni = 0; ni < 2; ni++)
                    mma16816(acc[mi][ni], ah[mi], bh[ni]);
            {
                uint32_t al[2][4];
                #pragma unroll
                for (int mi = 0; mi < 2; mi++)
                    ldmatrix_x4(al[mi], smem_u32(base + CG_T64 + (wm + mi * 16 + (lane & 15)) * AROW + aoff));
                #pragma unroll
                for (int mi = 0; mi < 2; mi++)
                    #pragma unroll
                    for (int ni = 0; ni < 2; ni++)
                        mma16816(acc[mi][ni], al[mi], bh[ni]);
            }
            {
                uint32_t bl[2][2];
                #pragma unroll
                for (int ni = 0; ni < 2; ni++)
                    ldmatrix_x2(bl[ni], smem_u32(base + 3 * CG_T64 + (wn + ni * 8 + (lane & 7)) * AROW + boff));
                #pragma unroll
                for (int mi = 0; mi < 2; mi++)
                    #pragma unroll
                    for (int ni = 0; ni < 2; ni++)
                        mma16816(acc[mi][ni], ah[mi], bl[ni]);
            }
        }
    }

    #pragma unroll
    for (int mi = 0; mi < 2; mi++) {
        int m0 = brow + wm + mi * 16 + (lane >> 2);
        #pragma unroll
        for (int ni = 0; ni < 2; ni++) {
            int n = bcol + wn + ni * 8 + (lane & 3) * 2;
            float2 b1v = *(const float2*)(b1 + n);
            #pragma unroll
            for (int half = 0; half < 2; half++) {
                int r = m0 + half * 8;
                if (r >= E_) continue;
                float c0 = acc[mi][ni][half * 2 + 0];
                float c1 = acc[mi][ni][half * 2 + 1];
                float2 a0v = *(const float2*)(ABX + (size_t)r * NBIG + n);
                float2 b0v = *(const float2*)(ABX + (size_t)r * NBIG + 512 + n);
                *(float2*)(Ap + (size_t)r * HID + n) =
                    make_float2(a0v.x + c0 + b1v.x, a0v.y + c1 + b1v.y);
                *(float2*)(Bp + (size_t)r * HID + n) =
                    make_float2(b0v.x - c0, b0v.y - c1);
            }
        }
    }
}

// ---------------- fused update GEMM: x_out = relu(Z@Wcat); writes xout + xcat -
__device__ __forceinline__ float4 z_load(
    const float* __restrict__ xin, int xld,
    const float* __restrict__ sintra, const float* __restrict__ sinter,
    const float* __restrict__ cintra, const float* __restrict__ cinter,
    int r, int kg)
{
    int seg = kg >> 7, d = kg & 127;
    if (seg == 0) {
        return *(const float4*)(xin + (size_t)r * xld + d);
    } else if (seg == 1) {
        float4 s = *(const float4*)(sintra + (size_t)r * NL + d);
        float4 xv = *(const float4*)(xin + (size_t)r * xld + d);
        float rc = 0.7f / (cintra[r] + 1.0f);
        return make_float4((s.x + xv.x) * rc, (s.y + xv.y) * rc,
                           (s.z + xv.z) * rc, (s.w + xv.w) * rc);
    } else {
        float4 s = *(const float4*)(sinter + (size_t)r * NL + d);
        float rc = 0.3f / fmaxf(cinter[r], 1.0f);
        return make_float4(s.x * rc, s.y * rc, s.z * rc, s.w * rc);
    }
}

__global__ void __launch_bounds__(256) upd_fused(
    int M,
    const float* __restrict__ xin, int xld,
    const float* __restrict__ sintra, const float* __restrict__ sinter,
    const float* __restrict__ cintra, const float* __restrict__ cinter,
    const float* __restrict__ Wcat,
    float* __restrict__ xout,
    __nv_bfloat16* __restrict__ xcat)
{
    const int BM = 64, BN = 64, BK = 16, KTOT = 3 * NL;
    __shared__ float As[2][BK][BM];
    __shared__ float Bs[2][BK][BN];
    const int tid  = threadIdx.x;
    const int brow = blockIdx.y * BM;
    const int bcol = blockIdx.x * BN;
    const int ar = tid >> 2, ac = (tid & 3) * 4;
    const int br = tid >> 4, bc = (tid & 15) * 4;
    const int tx = tid & 15, ty = tid >> 4;

    float4 areg = make_float4(0.f,0.f,0.f,0.f), breg;
    if (brow + ar < M) areg = z_load(xin, xld, sintra, sinter, cintra, cinter, brow + ar, ac);
    breg = *(const float4*)(Wcat + (size_t)br * NL + bcol + bc);
    As[0][ac+0][ar] = areg.x; As[0][ac+1][ar] = areg.y; As[0][ac+2][ar] = areg.z; As[0][ac+3][ar] = areg.w;
    *(float4*)&Bs[0][br][bc] = breg;
    __syncthreads();

    float acc[4][4];
    #pragma unroll
    for (int i = 0; i < 4; i++)
        #pragma unroll
        for (int j = 0; j < 4; j++) acc[i][j] = 0.f;

    int buf = 0;
    for (int k0 = BK; k0 < KTOT; k0 += BK) {
        areg = make_float4(0.f,0.f,0.f,0.f);
        if (brow + ar < M) areg = z_load(xin, xld, sintra, sinter, cintra, cinter, brow + ar, k0 + ac);
        breg = *(const float4*)(Wcat + (size_t)(k0 + br) * NL + bcol + bc);
        #pragma unroll
        for (int k = 0; k < BK; k++) {
            float av[4], bv[4];
            *(float4*)av = *(const float4*)&As[buf][k][ty * 4];
            *(float4*)bv = *(const float4*)&Bs[buf][k][tx * 4];
            #pragma unroll
            for (int i = 0; i < 4; i++)
                #pragma unroll
                for (int j = 0; j < 4; j++)
                    acc[i][j] = fmaf(av[i], bv[j], acc[i][j]);
        }
        int nb = buf ^ 1;
        As[nb][ac+0][ar] = areg.x; As[nb][ac+1][ar] = areg.y; As[nb][ac+2][ar] = areg.z; As[nb][ac+3][ar] = areg.w;
        *(float4*)&Bs[nb][br][bc] = breg;
        __syncthreads();
        buf = nb;
    }
    #pragma unroll
    for (int k = 0; k < BK; k++) {
        float av[4], bv[4];
        *(float4*)av = *(const float4*)&As[buf][k][ty * 4];
        *(float4*)bv = *(const float4*)&Bs[buf][k][tx * 4];
        #pragma unroll
        for (int i = 0; i < 4; i++)
            #pragma unroll
            for (int j = 0; j < 4; j++)
                acc[i][j] = fmaf(av[i], bv[j], acc[i][j]);
    }

    #pragma unroll
    for (int i = 0; i < 4; i++) {
        int r = brow + ty * 4 + i;
        if (r >= M) continue;
        float o[4];
        o[0] = fmaxf(acc[i][0], 0.f); o[1] = fmaxf(acc[i][1], 0.f);
        o[2] = fmaxf(acc[i][2], 0.f); o[3] = fmaxf(acc[i][3], 0.f);
        int col = bcol + tx * 4;
        *(float4*)(xout + (size_t)r * NL + col) = make_float4(o[0], o[1], o[2], o[3]);
        unsigned short hh[4], ll[4];
        #pragma unroll
        for (int j = 0; j < 4; j++) {
            __nv_bfloat16 hb = __float2bfloat16_rn(o[j]);
            __nv_bfloat16 lb = __float2bfloat16_rn(o[j] - __bfloat162float(hb));
            hh[j] = __bfloat16_as_ushort(hb);
            ll[j] = __bfloat16_as_ushort(lb);
        }
        __nv_bfloat16* xr = xcat + (size_t)r * KSC;
        *(ushort4*)(xr + col)       = make_ushort4(hh[0], hh[1], hh[2], hh[3]);
        *(ushort4*)(xr + 128 + col) = make_ushort4(ll[0], ll[1], ll[2], ll[3]);
    }
}

// ---------------- per-pair: 256 thr, 32 pairs/block (4 per warp) --------------
__global__ void __launch_bounds__(256) pair_kernel(
    const float* __restrict__ Ap, const float* __restrict__ Bp,
    const float* __restrict__ xin, int xld,
    const float* __restrict__ W2, const float* __restrict__ b2,
    const int* __restrict__ pair1, const int* __restrict__ pair2,
    const int* __restrict__ rtype, const int* __restrict__ targ,
    float* sintra, float* sinter, float* cintra, float* cinter,
    float* si_o, float* se_o, float* ci_o, float* ce_o,
    float* lossacc, float* logits_out,
    const float* lp_base, float* loss_out, int isLast,
    int P, int E)
{
    __shared__ float W2s0[HID], W2s1[HID], W2s2[HID];
    __shared__ float b2s[CLS];
    __shared__ float ce_s[8];
    int tid = threadIdx.x;
    for (int i = tid; i < HID; i += 256) {
        W2s0[i] = W2[i * 3 + 0];
        W2s1[i] = W2[i * 3 + 1];
        W2s2[i] = W2[i * 3 + 2];
    }
    if (tid < CLS) b2s[tid] = b2[tid];

    {
        long idx = (long)blockIdx.x * 256 + tid;
        long stride = (long)gridDim.x * 256;
        for (long i = idx; i < (long)E * NL; i += stride) { si_o[i] = 0.f; se_o[i] = 0.f; }
        for (long i = idx; i < E; i += stride) { ci_o[i] = 0.f; ce_o[i] = 0.f; }
    }
    __syncthreads();

    int warp = tid >> 5, lane = tid & 31;
    float ce_sum = 0.f;
    #pragma unroll
    for (int sub = 0; sub < 4; sub++) {
        int p = blockIdx.x * 32 + warp * 4 + sub;
        if (p >= P) continue;
        int p1 = pair1[p], p2 = pair2[p];
        const float4* a4 = (const float4*)(Ap + (size_t)p1 * HID);
        const float4* b4 = (const float4*)(Bp + (size_t)p2 * HID);
        float a0 = 0.f, a1 = 0.f, a2 = 0.f;
        #pragma unroll
        for (int j = 0; j < 4; j++) {
            int i4 = j * 32 + lane;
            float4 av = a4[i4], bv = b4[i4];
            float4 h;
            h.x = fmaxf(av.x + bv.x, 0.f);
            h.y = fmaxf(av.y + bv.y, 0.f);
            h.z = fmaxf(av.z + bv.z, 0.f);
            h.w = fmaxf(av.w + bv.w, 0.f);
            int base = i4 * 4;
            float4 w0 = *(const float4*)&W2s0[base];
            float4 w1 = *(const float4*)&W2s1[base];
            float4 w2 = *(const float4*)&W2s2[base];
            a0 = fmaf(h.x, w0.x, fmaf(h.y, w0.y, fmaf(h.z, w0.z, fmaf(h.w, w0.w, a0))));
            a1 = fmaf(h.x, w1.x, fmaf(h.y, w1.y, fmaf(h.z, w1.z, fmaf(h.w, w1.w, a1))));
            a2 = fmaf(h.x, w2.x, fmaf(h.y, w2.y, fmaf(h.z, w2.z, fmaf(h.w, w2.w, a2))));
        }
        #pragma unroll
        for (int o = 16; o; o >>= 1) {
            a0 += __shfl_xor_sync(0xffffffffu, a0, o);
            a1 += __shfl_xor_sync(0xffffffffu, a1, o);
            a2 += __shfl_xor_sync(0xffffffffu, a2, o);
        }
        float l0 = a0 + b2s[0], l1 = a1 + b2s[1], l2 = a2 + b2s[2];
        float m = fmaxf(l0, fmaxf(l1, l2));
        float s = expf(l0 - m) + expf(l1 - m) + expf(l2 - m);
        int tg = targ[p];
        float lt = (tg == 0) ? l0 : ((tg == 1) ? l1 : l2);
        ce_sum += logf(s) + m - lt;
        if (logits_out != nullptr && lane == 0) {
            logits_out[(size_t)p * 3 + 0] = l0;
            logits_out[(size_t)p * 3 + 1] = l1;
            logits_out[(size_t)p * 3 + 2] = l2;
        }
        int argm = 0; float mm = l0;
        if (l1 > mm) { mm = l1; argm = 1; }
        if (l2 > mm) { mm = l2; argm = 2; }
        bool conf = (1.0f / s) > 0.3f;
        int rt = rtype[p];
        if (conf && (argm == 1 || argm == 2)) {
            bool srcIs1 = (argm == 1);
            int src = srcIs1 ? p1 : p2;
            int dst = srcIs1 ? p2 : p1;
            float* sb = (rt == 0) ? sintra : sinter;
            float* cb = (rt == 0) ? cintra : cinter;
            const float* xs = xin + (size_t)src * xld;
            #pragma unroll
            for (int j = 0; j < NL / 32; j++) {
                int d = j * 32 + lane;
                atomicAdd(&sb[(size_t)dst * NL + d], xs[d]);
            }
            if (lane == 0) atomicAdd(&cb[dst], 1.0f);
        }
    }
    if (lane == 0) ce_s[warp] = ce_sum;
    __syncthreads();
    if (tid == 0) {
        float t = ce_s[0] + ce_s[1] + ce_s[2] + ce_s[3]
                + ce_s[4] + ce_s[5] + ce_s[6] + ce_s[7];
        atomicAdd(lossacc, t);
        if (isLast) {
            __threadfence();
            int v = atomicAdd(&g_done, 1);
            if (v == (int)gridDim.x - 1) {
                volatile const float* lv = lp_base;
                loss_out[0] = (lv[0] + lv[1] * 0.5f + lv[2] * (1.0f / 3.0f)) / (float)P;
            }
        }
    }
}

// ---------------- launch ------------------------------------------------------
extern "C" void kernel_launch(void* const* d_in, const int* in_sizes, int n_in,
                              void* d_out, int out_size)
{
    const float* sent   = (const float*)d_in[0];
    const float* Wproj  = (const float*)d_in[1];
    const float* W1     = (const float*)d_in[2];
    const float* b1     = (const float*)d_in[3];
    const float* W2     = (const float*)d_in[4];
    const float* b2     = (const float*)d_in[5];
    const float* Wself  = (const float*)d_in[6];
    const float* Wintra = (const float*)d_in[7];
    const float* Winter = (const float*)d_in[8];
    const int* esent  = (const int*)d_in[9];
    const int* estart = (const int*)d_in[10];
    const int* elen   = (const int*)d_in[11];
    const int* pair1  = (const int*)d_in[12];
    const int* pair2  = (const int*)d_in[13];
    const int* rtype  = (const int*)d_in[14];
    const int* targ   = (const int*)d_in[15];
    float* out = (float*)d_out;

    int E = in_sizes[9];
    int P = in_sizes[12];
    if (E > E_MAX) E = E_MAX;
    if (P > P_MAX) P = P_MAX;

    __nv_bfloat16 *Acat, *Bcat, *W1cT, *xcat;
    float *ABX, *Ap, *Bp, *lp, *Wcat, *part;
    float *xb[2], *si[2], *se[2], *ci[2], *ce[2];
    cudaGetSymbolAddress((void**)&Acat, g_Acat);
    cudaGetSymbolAddress((void**)&Bcat, g_Bcat);
    cudaGetSymbolAddress((void**)&W1cT, g_W1cT);
    cudaGetSymbolAddress((void**)&xcat, g_xcat);
    cudaGetSymbolAddress((void**)&ABX,  g_ABX);
    cudaGetSymbolAddress((void**)&Ap,   g_Ap);
    cudaGetSymbolAddress((void**)&Bp,   g_Bp);
    cudaGetSymbolAddress((void**)&Wcat, g_Wcat);
    cudaGetSymbolAddress((void**)&lp,   g_losspart);
    cudaGetSymbolAddress((void**)&part, g_part);
    {
        float* base;
        cudaGetSymbolAddress((void**)&base, g_xbuf);
        xb[0] = base; xb[1] = base + E_MAX * NL;
        cudaGetSymbolAddress((void**)&base, g_sintra);
        si[0] = base; si[1] = base + E_MAX * NL;
        cudaGetSymbolAddress((void**)&base, g_sinter);
        se[0] = base; se[1] = base + E_MAX * NL;
        cudaGetSymbolAddress((void**)&base, g_cintra);
        ci[0] = base; ci[1] = base + E_MAX;
        cudaGetSymbolAddress((void**)&base, g_cinter);
        ce[0] = base; ce[1] = base + E_MAX;
    }

    int loff = out_size - 3 * P;
    if (loff < 0) loff = 0;
    float* logits_out = out + loff;

    // 1) one setup launch (also resets g_done)
    {
        int prepb = (int)((3L * NL * NL + (long)E * NL + E + 4 + 1 + 255) / 256);
        int total = E + WTR_B + WTRC_B + prepb;
        setup_kernel<<<total, 256>>>(sent, esent, estart, elen,
                                     W1, Wproj, Wself, Wintra, Winter, E);
    }

    // 2) split-K tensor-core big GEMM + fixup (sums partials, emits xcat)
    cudaFuncSetAttribute(mma_gemm_sk, cudaFuncAttributeMaxDynamicSharedMemorySize, SK_SMEM);
    cudaFuncSetAttribute(cgemm_mma, cudaFuncAttributeMaxDynamicSharedMemorySize, CG_SMEM);
    {
        dim3 g(NBIG / 128, (E_MAX + 127) / 128, 2);   // 9 x 16 x 2 = 288 CTAs
        mma_gemm_sk<<<g, 256, SK_SMEM>>>(E, Acat, Bcat, part);
        fixup_kernel<<<1184, 256>>>(E, part, part + (size_t)E_MAX * NBIG, ABX, xcat);
    }

    // 3) three iterations
    for (int it = 0; it < 3; it++) {
        int ph = it & 1, po = ph ^ 1;
        const float* xin = (it == 0) ? (ABX + 1024) : xb[(it - 1) & 1];
        int xld = (it == 0) ? NBIG : NL;
        float* xout = xb[it & 1];

        {
            dim3 g(HID / 64, (E + 63) / 64);      // 8 x 32 = 256 CTAs
            cgemm_mma<<<g, 256, CG_SMEM>>>(E, xcat, W1cT, ABX, b1, Ap, Bp);
        }
        pair_kernel<<<(P + 31) / 32, 256>>>(Ap, Bp, xin, xld, W2, b2,
                                          pair1, pair2, rtype, targ,
                                          si[ph], se[ph], ci[ph], ce[ph],
                                          si[po], se[po], ci[po], ce[po],
                                          lp + it, (it == 2) ? logits_out : nullptr,
                                          lp, out, (it == 2) ? 1 : 0, P, E);
        if (it < 2) {
            dim3 g(NL / 64, (E + 63) / 64);
            upd_fused<<<g, 256>>>(E, xin, xld,
                                  si[ph], se[ph], ci[ph], ce[ph],
                                  Wcat, xout, xcat);
        }
    }
}